// round 1
// baseline (speedup 1.0000x reference)
#include <cuda_runtime.h>
#include <math.h>

#define BATCH 8
#define SEQ   2048
#define DIM   512
#define MR    (BATCH*SEQ)
#define HALF  (DIM/2)

// ---------------- static scratch (device globals; no runtime alloc) ----------------
__device__ float g_wc[3*DIM*DIM];            // conv weights transposed: [k=1536][dout=512]
__device__ float g_wqkv[DIM*3*DIM];          // qkv weights transposed: [d=512][e=1536]
__device__ float g_xconv[(size_t)MR*DIM];    // conv output
__device__ float g_xnorm[(size_t)MR*DIM];    // rmsnorm(conv)
__device__ float g_qkv[(size_t)MR*3*DIM];    // raw q|k|v
__device__ float g_q[(size_t)MR*DIM];        // normed + rope'd q
__device__ float g_k[(size_t)MR*DIM];        // normed + rope'd k
__device__ float g_v[(size_t)MR*DIM];        // v
__device__ float g_scores[(size_t)BATCH*SEQ*SEQ]; // scores, then exp(p - m)
__device__ float g_invZ[MR];
__device__ float g_wbar[MR];
__device__ float g_cos[SEQ*HALF];
__device__ float g_sin[SEQ*HALF];
__device__ float g_part[BATCH*16*DIM];

// ---------------- helpers ----------------
__device__ __forceinline__ float warp_sum(float v){
    #pragma unroll
    for (int o=16;o;o>>=1) v += __shfl_xor_sync(0xffffffffu, v, o);
    return v;
}
__device__ __forceinline__ float warp_max(float v){
    #pragma unroll
    for (int o=16;o;o>>=1) v = fmaxf(v, __shfl_xor_sync(0xffffffffu, v, o));
    return v;
}

// ---------------- weight re-layout ----------------
__global__ void prep_weights(const float* __restrict__ conv_w,
                             const float* __restrict__ Wq,
                             const float* __restrict__ Wk,
                             const float* __restrict__ Wv)
{
    int idx = blockIdx.x*256 + threadIdx.x;
    if (idx >= 3*DIM*DIM) return;
    {   // conv: idx = kk*512 + dout, kk = t*512 + din
        int dout = idx % DIM;
        int kk   = idx / DIM;
        int din  = kk % DIM;
        int t    = kk / DIM;
        g_wc[idx] = conv_w[(dout*DIM + din)*3 + t];
    }
    {   // qkv: idx = d*1536 + j
        int j = idx % (3*DIM);
        int d = idx / (3*DIM);
        float w;
        if (j < DIM)        w = Wq[j*DIM + d];
        else if (j < 2*DIM) w = Wk[(j-DIM)*DIM + d];
        else                w = Wv[(j-2*DIM)*DIM + d];
        g_wqkv[idx] = w;
    }
}

// ---------------- rope tables (double precision, once per launch) ----------------
__global__ void rope_tables_k()
{
    int i = threadIdx.x;   // 0..255
    int s = blockIdx.x;    // 0..2047
    double inv = pow(10000.0, -((double)(2*i)) / 512.0);
    double arg = (double)s * inv;
    g_cos[s*HALF + i] = (float)cos(arg);
    g_sin[s*HALF + i] = (float)sin(arg);
}

// ---------------- tiled SGEMM ----------------
// MODE 0: C[M,N] = A[M,K] * B[K,N]                     (A lda=K, B ldb=N)
// MODE 1: implicit im2col conv: A row m = x + m*512-512 (masked), B = g_wc
// MODE 2: NT per-batch: C[q,k] = sum_d A[q,d]*B[k,d], batch via blockIdx.z
#define BM 128
#define BN 128
#define BK 16

template<int MODE>
__global__ __launch_bounds__(256,2) void gemm_k(
    const float* __restrict__ A, const float* __restrict__ Bm,
    float* __restrict__ C, int Nd, int Kd,
    const float* __restrict__ bias, float scale)
{
    __shared__ float As[BM][BK];
    __shared__ float Bs[BK][BN];
    const int bm = blockIdx.y * BM;
    const int bn = blockIdx.x * BN;
    if (MODE == 2) {
        size_t z = blockIdx.z;
        A  += z * (size_t)SEQ * DIM;
        Bm += z * (size_t)SEQ * DIM;
        C  += z * (size_t)SEQ * SEQ;
    }
    const int tid = threadIdx.x;
    const int tx = tid & 15;   // N direction (16)
    const int ty = tid >> 4;   // M direction (16)

    float acc[8][8];
    #pragma unroll
    for (int i=0;i<8;i++)
        #pragma unroll
        for (int j=0;j<8;j++) acc[i][j]=0.f;

    for (int k0 = 0; k0 < Kd; k0 += BK) {
        // ---- A tile: 128 x 16, float4 along k; stored [m][k] (conflict-free) ----
        #pragma unroll
        for (int it=0; it<2; it++) {
            int i  = it*256 + tid;    // 0..511 float4 slots
            int m  = i >> 2;
            int kq = (i & 3) * 4;
            float4 va;
            if (MODE == 1) {
                int gm = bm + m;
                int s  = gm & (SEQ-1);
                int kg = k0 + kq;
                int t  = kg >> 9;     // window tap 0..2 (float4 never crosses a tap)
                if ((s==0 && t==0) || (s==SEQ-1 && t==2)) {
                    va = make_float4(0.f,0.f,0.f,0.f);
                } else {
                    va = *(const float4*)&A[(size_t)gm*DIM + kg - DIM];
                }
            } else {
                va = *(const float4*)&A[(size_t)(bm+m)*Kd + k0 + kq];
            }
            *(float4*)&As[m][kq] = va;
        }
        // ---- B tile: 16 x 128 ----
        if (MODE == 2) {
            #pragma unroll
            for (int it=0; it<2; it++) {
                int i  = it*256 + tid;
                int n  = i >> 2;
                int kq = (i & 3) * 4;
                float4 vb = *(const float4*)&Bm[(size_t)(bn+n)*Kd + k0 + kq];
                Bs[kq+0][n] = vb.x;
                Bs[kq+1][n] = vb.y;
                Bs[kq+2][n] = vb.z;
                Bs[kq+3][n] = vb.w;
            }
        } else {
            #pragma unroll
            for (int it=0; it<2; it++) {
                int i  = it*256 + tid;
                int kk = i >> 5;
                int n4 = (i & 31) * 4;
                float4 vb = *(const float4*)&Bm[(size_t)(k0+kk)*Nd + bn + n4];
                *(float4*)&Bs[kk][n4] = vb;
            }
        }
        __syncthreads();
        // ---- compute 8x8 per thread, split 4+4 in each dim for conflict-free LDS.128 ----
        #pragma unroll
        for (int kk=0; kk<BK; kk++) {
            float a[8], b[8];
            #pragma unroll
            for (int i=0;i<4;i++) {
                a[i]   = As[ty*4+i][kk];
                a[4+i] = As[64+ty*4+i][kk];
            }
            float4 b0 = *(const float4*)&Bs[kk][tx*4];
            float4 b1 = *(const float4*)&Bs[kk][64+tx*4];
            b[0]=b0.x;b[1]=b0.y;b[2]=b0.z;b[3]=b0.w;
            b[4]=b1.x;b[5]=b1.y;b[6]=b1.z;b[7]=b1.w;
            #pragma unroll
            for (int i=0;i<8;i++)
                #pragma unroll
                for (int j=0;j<8;j++)
                    acc[i][j] += a[i]*b[j];
        }
        __syncthreads();
    }
    // ---- epilogue ----
    #pragma unroll
    for (int ib=0; ib<2; ib++)
    #pragma unroll
    for (int i=0;i<4;i++) {
        int row = bm + ib*64 + ty*4 + i;
        #pragma unroll
        for (int jb=0; jb<2; jb++) {
            int col = bn + jb*64 + tx*4;
            float4 o;
            o.x = acc[ib*4+i][jb*4+0]*scale;
            o.y = acc[ib*4+i][jb*4+1]*scale;
            o.z = acc[ib*4+i][jb*4+2]*scale;
            o.w = acc[ib*4+i][jb*4+3]*scale;
            if (bias) {
                float4 bb = *(const float4*)&bias[col];
                o.x+=bb.x; o.y+=bb.y; o.z+=bb.z; o.w+=bb.w;
            }
            *(float4*)&C[(size_t)row*Nd + col] = o;
        }
    }
}

// ---------------- rmsnorm(conv) ----------------
__global__ void rmsnorm_pre_k(const float* __restrict__ pre_g)
{
    int m = blockIdx.x;
    int tid = threadIdx.x; // 128
    const float* row = g_xconv + (size_t)m*DIM;
    float4 v = *(const float4*)&row[tid*4];
    float ss = v.x*v.x + v.y*v.y + v.z*v.z + v.w*v.w;
    ss = warp_sum(ss);
    __shared__ float sm[4];
    if ((tid&31)==0) sm[tid>>5] = ss;
    __syncthreads();
    float tot = sm[0]+sm[1]+sm[2]+sm[3];
    float r = rsqrtf(tot * (1.f/DIM) + 1e-6f);
    float4 g = *(const float4*)&pre_g[tid*4];
    float4 o;
    o.x = v.x*r*g.x; o.y = v.y*r*g.y; o.z = v.z*r*g.z; o.w = v.w*r*g.w;
    *(float4*)&g_xnorm[(size_t)m*DIM + tid*4] = o;
}

// ---------------- rmsnorm + rope on q/k, copy v ----------------
__global__ void qkv_post_k(const float* __restrict__ q_g, const float* __restrict__ k_g)
{
    int m = blockIdx.x;
    int tid = threadIdx.x; // 128
    int s = m & (SEQ-1);
    const float* row = g_qkv + (size_t)m*3*DIM;
    float2 qa = *(const float2*)&row[2*tid];
    float2 qb = *(const float2*)&row[2*(tid+128)];
    float2 ka = *(const float2*)&row[DIM + 2*tid];
    float2 kb = *(const float2*)&row[DIM + 2*(tid+128)];
    float sq = qa.x*qa.x+qa.y*qa.y+qb.x*qb.x+qb.y*qb.y;
    float sk = ka.x*ka.x+ka.y*ka.y+kb.x*kb.x+kb.y*kb.y;
    sq = warp_sum(sq); sk = warp_sum(sk);
    __shared__ float smq[4], smk[4];
    if ((tid&31)==0) { smq[tid>>5]=sq; smk[tid>>5]=sk; }
    __syncthreads();
    float rq = rsqrtf((smq[0]+smq[1]+smq[2]+smq[3]) * (1.f/DIM) + 1e-6f);
    float rk = rsqrtf((smk[0]+smk[1]+smk[2]+smk[3]) * (1.f/DIM) + 1e-6f);

    #pragma unroll
    for (int pp=0; pp<2; pp++) {
        int p = tid + pp*128;                 // pair index 0..255
        float c  = g_cos[s*HALF + p];
        float sn = g_sin[s*HALF + p];
        float2 qv = pp ? qb : qa;
        float2 kv = pp ? kb : ka;
        float x0 = qv.x*rq*q_g[2*p], x1 = qv.y*rq*q_g[2*p+1];
        float2 qo; qo.x = x0*c - x1*sn; qo.y = x0*sn + x1*c;
        *(float2*)&g_q[(size_t)m*DIM + 2*p] = qo;
        float y0 = kv.x*rk*k_g[2*p], y1 = kv.y*rk*k_g[2*p+1];
        float2 ko; ko.x = y0*c - y1*sn; ko.y = y0*sn + y1*c;
        *(float2*)&g_k[(size_t)m*DIM + 2*p] = ko;
    }
    float4 vv = *(const float4*)&row[2*DIM + 4*tid];
    *(float4*)&g_v[(size_t)m*DIM + 4*tid] = vv;
}

// ---------------- softmax rows: scores -> exp(s - m), store 1/Z ----------------
__global__ void softmax_rows_k()
{
    int m = blockIdx.x;
    float* row = g_scores + (size_t)m*SEQ;
    int tid = threadIdx.x; // 256
    float v[8];
    float mx = -1e30f;
    #pragma unroll
    for (int c=0;c<8;c++) { v[c] = row[tid + c*256]; mx = fmaxf(mx, v[c]); }
    mx = warp_max(mx);
    __shared__ float sm1[8], sm2[8];
    if ((tid&31)==0) sm1[tid>>5]=mx;
    __syncthreads();
    mx = sm1[0];
    #pragma unroll
    for (int w=1;w<8;w++) mx = fmaxf(mx, sm1[w]);
    float ssum = 0.f;
    #pragma unroll
    for (int c=0;c<8;c++){ v[c] = expf(v[c]-mx); ssum += v[c]; }
    ssum = warp_sum(ssum);
    if ((tid&31)==0) sm2[tid>>5]=ssum;
    __syncthreads();
    float Z = 0.f;
    #pragma unroll
    for (int w=0;w<8;w++) Z += sm2[w];
    #pragma unroll
    for (int c=0;c<8;c++) row[tid + c*256] = v[c];
    if (tid==0) g_invZ[m] = 1.f/Z;
}

// ---------------- wbar[b,k] = sum_q p[b,q,k] / Z[b,q] ----------------
__global__ void colsum_k()
{
    int b = blockIdx.y;
    int k = blockIdx.x*256 + threadIdx.x;
    const float* p  = g_scores + (size_t)b*SEQ*SEQ + k;
    const float* iz = g_invZ + b*SEQ;
    float acc = 0.f;
    #pragma unroll 8
    for (int q=0; q<SEQ; q++)
        acc += p[(size_t)q*SEQ] * iz[q];
    g_wbar[b*SEQ + k] = acc;
}

// ---------------- out[b,d] = (sum_s x + sum_k wbar*v) / S ----------------
__global__ void final_acc_k(const float* __restrict__ x)
{
    int b = blockIdx.y, c = blockIdx.x;
    int d = threadIdx.x; // 512
    size_t base = ((size_t)b*SEQ + (size_t)c*128)*DIM + d;
    const float* wb = g_wbar + b*SEQ + c*128;
    float a = 0.f;
    #pragma unroll 4
    for (int s=0;s<128;s++)
        a += x[base + (size_t)s*DIM] + wb[s]*g_v[base + (size_t)s*DIM];
    g_part[(b*16+c)*DIM + d] = a;
}
__global__ void final_reduce_k(float* __restrict__ out)
{
    int b = blockIdx.x, d = threadIdx.x;
    float a = 0.f;
    #pragma unroll
    for (int c=0;c<16;c++) a += g_part[(b*16+c)*DIM + d];
    out[b*DIM + d] = a * (1.f/SEQ);
}

// ---------------- launch ----------------
extern "C" void kernel_launch(void* const* d_in, const int* in_sizes, int n_in,
                              void* d_out, int out_size)
{
    const float* x      = (const float*)d_in[0];
    const float* conv_w = (const float*)d_in[1];
    const float* conv_b = (const float*)d_in[2];
    const float* pre_g  = (const float*)d_in[3];
    const float* q_g    = (const float*)d_in[4];
    const float* k_g    = (const float*)d_in[5];
    const float* Wq     = (const float*)d_in[6];
    const float* Wk     = (const float*)d_in[7];
    const float* Wv     = (const float*)d_in[8];
    float* out = (float*)d_out;

    float *wc, *wqkv, *xconv, *xnorm, *qkv, *q, *k, *scores;
    cudaGetSymbolAddress((void**)&wc, g_wc);
    cudaGetSymbolAddress((void**)&wqkv, g_wqkv);
    cudaGetSymbolAddress((void**)&xconv, g_xconv);
    cudaGetSymbolAddress((void**)&xnorm, g_xnorm);
    cudaGetSymbolAddress((void**)&qkv, g_qkv);
    cudaGetSymbolAddress((void**)&q, g_q);
    cudaGetSymbolAddress((void**)&k, g_k);
    cudaGetSymbolAddress((void**)&scores, g_scores);

    prep_weights<<<(3*DIM*DIM + 255)/256, 256>>>(conv_w, Wq, Wk, Wv);
    rope_tables_k<<<SEQ, HALF>>>();

    // conv as implicit-im2col GEMM: M=16384, N=512, K=1536 (+bias)
    gemm_k<1><<<dim3(DIM/BN, MR/BM), 256>>>(x, wc, xconv, DIM, 3*DIM, conv_b, 1.f);
    rmsnorm_pre_k<<<MR, 128>>>(pre_g);

    // fused QKV GEMM: M=16384, N=1536, K=512
    gemm_k<0><<<dim3(3*DIM/BN, MR/BM), 256>>>(xnorm, wqkv, qkv, 3*DIM, DIM, nullptr, 1.f);
    qkv_post_k<<<MR, 128>>>(q_g, k_g);

    // scores: per-batch NT GEMM, M=N=2048, K=512, scale=1/sqrt(512)
    gemm_k<2><<<dim3(SEQ/BN, SEQ/BM, BATCH), 256>>>(q, k, scores, SEQ, DIM,
                                                    nullptr, 0.044194173824159216f);
    softmax_rows_k<<<MR, 256>>>();
    colsum_k<<<dim3(SEQ/256, BATCH), 256>>>();
    final_acc_k<<<dim3(16, BATCH), DIM>>>(x);
    final_reduce_k<<<BATCH, DIM>>>(out);
}

// round 3
// speedup vs baseline: 1.5201x; 1.5201x over previous
#include <cuda_runtime.h>
#include <cstdint>
#include <math.h>
#include <mma.h>

using namespace nvcuda;

#define BATCH 8
#define SEQ   2048
#define DIM   512
#define MR    (BATCH*SEQ)
#define HALF  (DIM/2)

// ---------------- static scratch ----------------
__device__ float g_wc[3*DIM*DIM];            // conv weights: [dout=512][k=1536] K-major
__device__ float g_wqkv[3*DIM*DIM];          // concat(Wq,Wk,Wv): [e=1536][d=512] K-major
__device__ float g_xconv[(size_t)MR*DIM];
__device__ float g_xnorm[(size_t)MR*DIM];
__device__ float g_qkv[(size_t)MR*3*DIM];
__device__ float g_q[(size_t)MR*DIM];
__device__ float g_k[(size_t)MR*DIM];
__device__ float g_v[(size_t)MR*DIM];
__device__ float g_scores[(size_t)BATCH*SEQ*SEQ];
__device__ float g_invZ[MR];
__device__ float g_wbar[MR];
__device__ float g_cos[SEQ*HALF];
__device__ float g_sin[SEQ*HALF];
__device__ float g_part[BATCH*16*DIM];

// ---------------- helpers ----------------
__device__ __forceinline__ uint32_t smem_u32(const void* p){
    uint32_t a;
    asm("{ .reg .u64 t; cvta.to.shared.u64 t, %1; cvt.u32.u64 %0, t; }" : "=r"(a) : "l"(p));
    return a;
}
__device__ __forceinline__ void cp_async16(uint32_t dst, const void* src, bool pred){
    int sz = pred ? 16 : 0;   // ZFILL when masked
    asm volatile("cp.async.cg.shared.global [%0], [%1], 16, %2;"
                 :: "r"(dst), "l"(src), "r"(sz));
}
__device__ __forceinline__ void cp_async_commit(){
    asm volatile("cp.async.commit_group;" ::: "memory");
}
template<int N>
__device__ __forceinline__ void cp_async_wait(){
    asm volatile("cp.async.wait_group %0;" :: "n"(N) : "memory");
}
__device__ __forceinline__ float warp_sum(float v){
    #pragma unroll
    for (int o=16;o;o>>=1) v += __shfl_xor_sync(0xffffffffu, v, o);
    return v;
}
__device__ __forceinline__ float warp_max(float v){
    #pragma unroll
    for (int o=16;o;o>>=1) v = fmaxf(v, __shfl_xor_sync(0xffffffffu, v, o));
    return v;
}

// ---------------- weight re-layout ----------------
__global__ void prep_weights(const float* __restrict__ conv_w,
                             const float* __restrict__ Wq,
                             const float* __restrict__ Wk,
                             const float* __restrict__ Wv)
{
    int idx = blockIdx.x*256 + threadIdx.x;
    if (idx >= 3*DIM*DIM) return;
    {   // conv: [dout][kk], kk = t*512 + din
        int kk   = idx % (3*DIM);
        int dout = idx / (3*DIM);
        int din  = kk % DIM;
        int t    = kk / DIM;
        g_wc[idx] = conv_w[(dout*DIM + din)*3 + t];
    }
    {   // qkv concat: [e_cat=1536][d=512]
        g_wqkv[idx] = (idx < DIM*DIM) ? Wq[idx]
                    : (idx < 2*DIM*DIM) ? Wk[idx - DIM*DIM]
                    : Wv[idx - 2*DIM*DIM];
    }
}

__global__ void rope_tables_k()
{
    int i = threadIdx.x;
    int s = blockIdx.x;
    double inv = pow(10000.0, -((double)(2*i)) / 512.0);
    double arg = (double)s * inv;
    g_cos[s*HALF + i] = (float)cos(arg);
    g_sin[s*HALF + i] = (float)sin(arg);
}

// ---------------- WMMA tf32 GEMM ----------------
// C[M,N] = A[M,K] * B[N,K]^T  (A row-major K-major, B row-major K-major = col-major k x n)
// MODE 0: generic.  MODE 1: A = implicit im2col of x (conv, +bias).  MODE 2: batched via z (+scale).
// Block tile 128x128x32, 256 threads = 8 warps (2 x 4), warp tile 64x32.
// SMEM: double-buffered A(128x40) + B(128x40) fp32; same space reused by the epilogue.
#define TLD    40            // padded leading dim (floats)
#define TFLT   (128*TLD)     // floats per tile (5120)
#define BUFLT  (2*TFLT)      // floats per buffer (A+B) (10240)
#define GSMEM  (2*BUFLT*4)   // total dynamic smem bytes (81920)

template<int MODE>
__global__ __launch_bounds__(256,2) void mma_gemm_k(
    const float* __restrict__ A, const float* __restrict__ Bm,
    float* __restrict__ C, int Nd, int Kd,
    const float* __restrict__ bias, float scale)
{
    extern __shared__ float sm[];
    const uint32_t sb = smem_u32(sm);
    const int tid = threadIdx.x;
    const int wid = tid >> 5, lane = tid & 31;
    const int wm = wid & 1, wn = wid >> 1;        // 2 x 4 warp grid
    const int bm = blockIdx.y*128, bn = blockIdx.x*128;
    if (MODE == 2) {
        size_t z = blockIdx.z;
        A  += z * (size_t)SEQ * DIM;
        Bm += z * (size_t)SEQ * DIM;
        C  += z * (size_t)SEQ * SEQ;
    }

    wmma::fragment<wmma::accumulator,16,16,8,float> acc[4][2];
    #pragma unroll
    for (int i=0;i<4;i++)
        #pragma unroll
        for (int j=0;j<2;j++) wmma::fill_fragment(acc[i][j], 0.f);

    const int nIter = Kd / 32;

    auto load_tiles = [&](int it, int buf){
        const int k0 = it*32;
        const uint32_t abase = sb + (buf*BUFLT)*4;
        const uint32_t bbase = abase + TFLT*4;
        #pragma unroll
        for (int l=0;l<4;l++){
            int i   = l*256 + tid;       // 0..1023
            int row = i >> 3;
            int kq  = (i & 7) * 4;
            // A
            {
                const float* src; bool pred = true;
                if (MODE == 1) {
                    int gm = bm + row;
                    int s  = gm & (SEQ-1);
                    int kg = k0 + kq;
                    int t  = kg >> 9;
                    pred = !((s==0 && t==0) || (s==SEQ-1 && t==2));
                    src = pred ? (A + (size_t)gm*DIM + kg - DIM) : A;
                } else {
                    src = A + (size_t)(bm+row)*Kd + k0 + kq;
                }
                cp_async16(abase + (row*TLD + kq)*4, src, pred);
            }
            // B
            cp_async16(bbase + (row*TLD + kq)*4,
                       Bm + (size_t)(bn+row)*Kd + k0 + kq, true);
        }
    };

    load_tiles(0, 0);
    cp_async_commit();

    for (int it = 0; it < nIter; ++it) {
        const int buf = it & 1;
        if (it + 1 < nIter) {
            load_tiles(it+1, buf^1);
            cp_async_commit();
            cp_async_wait<1>();
        } else {
            cp_async_wait<0>();
        }
        __syncthreads();

        const float* Ab = sm + buf*BUFLT;
        const float* Bb = Ab + TFLT;
        #pragma unroll
        for (int ks = 0; ks < 4; ks++) {
            wmma::fragment<wmma::matrix_a,16,16,8,wmma::precision::tf32,wmma::row_major> af[4];
            wmma::fragment<wmma::matrix_b,16,16,8,wmma::precision::tf32,wmma::col_major> bf[2];
            #pragma unroll
            for (int i=0;i<4;i++){
                wmma::load_matrix_sync(af[i], Ab + (wm*64 + i*16)*TLD + ks*8, TLD);
                #pragma unroll
                for (int e=0;e<af[i].num_elements;e++)
                    af[i].x[e] = wmma::__float_to_tf32(af[i].x[e]);
            }
            #pragma unroll
            for (int j=0;j<2;j++){
                wmma::load_matrix_sync(bf[j], Bb + (wn*32 + j*16)*TLD + ks*8, TLD);
                #pragma unroll
                for (int e=0;e<bf[j].num_elements;e++)
                    bf[j].x[e] = wmma::__float_to_tf32(bf[j].x[e]);
            }
            #pragma unroll
            for (int i=0;i<4;i++)
                #pragma unroll
                for (int j=0;j<2;j++)
                    wmma::mma_sync(acc[i][j], af[i], bf[j], acc[i][j]);
        }
        __syncthreads();
    }

    // ---- epilogue via per-warp smem tile (64x32, ld=TLD) ----
    float* w = sm + wid * (64*TLD);
    #pragma unroll
    for (int i=0;i<4;i++)
        #pragma unroll
        for (int j=0;j<2;j++)
            wmma::store_matrix_sync(w + (i*16)*TLD + j*16, acc[i][j], TLD, wmma::mem_row_major);
    __syncwarp();

    const int tx = lane & 7, ty = lane >> 3;   // 8 f4-cols x 4 rows
    #pragma unroll
    for (int r=0;r<16;r++){
        int row  = r*4 + ty;
        int col  = tx*4;
        float4 o = *(float4*)&w[row*TLD + col];
        o.x *= scale; o.y *= scale; o.z *= scale; o.w *= scale;
        int gcol = bn + wn*32 + col;
        if (MODE == 1) {
            float4 bb = *(const float4*)&bias[gcol];
            o.x += bb.x; o.y += bb.y; o.z += bb.z; o.w += bb.w;
        }
        int grow = bm + wm*64 + row;
        *(float4*)&C[(size_t)grow*Nd + gcol] = o;
    }
}

// ---------------- rmsnorm(conv) ----------------
__global__ void rmsnorm_pre_k(const float* __restrict__ pre_g)
{
    int m = blockIdx.x;
    int tid = threadIdx.x; // 128
    const float* row = g_xconv + (size_t)m*DIM;
    float4 v = *(const float4*)&row[tid*4];
    float ss = v.x*v.x + v.y*v.y + v.z*v.z + v.w*v.w;
    ss = warp_sum(ss);
    __shared__ float smm[4];
    if ((tid&31)==0) smm[tid>>5] = ss;
    __syncthreads();
    float tot = smm[0]+smm[1]+smm[2]+smm[3];
    float r = rsqrtf(tot * (1.f/DIM) + 1e-6f);
    float4 g = *(const float4*)&pre_g[tid*4];
    float4 o;
    o.x = v.x*r*g.x; o.y = v.y*r*g.y; o.z = v.z*r*g.z; o.w = v.w*r*g.w;
    *(float4*)&g_xnorm[(size_t)m*DIM + tid*4] = o;
}

// ---------------- rmsnorm + rope on q/k, copy v ----------------
__global__ void qkv_post_k(const float* __restrict__ q_g, const float* __restrict__ k_g)
{
    int m = blockIdx.x;
    int tid = threadIdx.x; // 128
    int s = m & (SEQ-1);
    const float* row = g_qkv + (size_t)m*3*DIM;
    float2 qa = *(const float2*)&row[2*tid];
    float2 qb = *(const float2*)&row[2*(tid+128)];
    float2 ka = *(const float2*)&row[DIM + 2*tid];
    float2 kb = *(const float2*)&row[DIM + 2*(tid+128)];
    float sq = qa.x*qa.x+qa.y*qa.y+qb.x*qb.x+qb.y*qb.y;
    float sk = ka.x*ka.x+ka.y*ka.y+kb.x*kb.x+kb.y*kb.y;
    sq = warp_sum(sq); sk = warp_sum(sk);
    __shared__ float smq[4], smk[4];
    if ((tid&31)==0) { smq[tid>>5]=sq; smk[tid>>5]=sk; }
    __syncthreads();
    float rq = rsqrtf((smq[0]+smq[1]+smq[2]+smq[3]) * (1.f/DIM) + 1e-6f);
    float rk = rsqrtf((smk[0]+smk[1]+smk[2]+smk[3]) * (1.f/DIM) + 1e-6f);

    #pragma unroll
    for (int pp=0; pp<2; pp++) {
        int p = tid + pp*128;
        float c  = g_cos[s*HALF + p];
        float sn = g_sin[s*HALF + p];
        float2 qv = pp ? qb : qa;
        float2 kv = pp ? kb : ka;
        float x0 = qv.x*rq*q_g[2*p], x1 = qv.y*rq*q_g[2*p+1];
        float2 qo; qo.x = x0*c - x1*sn; qo.y = x0*sn + x1*c;
        *(float2*)&g_q[(size_t)m*DIM + 2*p] = qo;
        float y0 = kv.x*rk*k_g[2*p], y1 = kv.y*rk*k_g[2*p+1];
        float2 ko; ko.x = y0*c - y1*sn; ko.y = y0*sn + y1*c;
        *(float2*)&g_k[(size_t)m*DIM + 2*p] = ko;
    }
    float4 vv = *(const float4*)&row[2*DIM + 4*tid];
    *(float4*)&g_v[(size_t)m*DIM + 4*tid] = vv;
}

// ---------------- softmax rows ----------------
__global__ void softmax_rows_k()
{
    int m = blockIdx.x;
    float* row = g_scores + (size_t)m*SEQ;
    int tid = threadIdx.x; // 256
    float v[8];
    float mx = -1e30f;
    #pragma unroll
    for (int c=0;c<8;c++) { v[c] = row[tid + c*256]; mx = fmaxf(mx, v[c]); }
    mx = warp_max(mx);
    __shared__ float sm1[8], sm2[8];
    if ((tid&31)==0) sm1[tid>>5]=mx;
    __syncthreads();
    mx = sm1[0];
    #pragma unroll
    for (int w=1;w<8;w++) mx = fmaxf(mx, sm1[w]);
    float ssum = 0.f;
    #pragma unroll
    for (int c=0;c<8;c++){ v[c] = expf(v[c]-mx); ssum += v[c]; }
    ssum = warp_sum(ssum);
    if ((tid&31)==0) sm2[tid>>5]=ssum;
    __syncthreads();
    float Z = 0.f;
    #pragma unroll
    for (int w=0;w<8;w++) Z += sm2[w];
    #pragma unroll
    for (int c=0;c<8;c++) row[tid + c*256] = v[c];
    if (tid==0) g_invZ[m] = 1.f/Z;
}

// ---------------- wbar[b,k] = sum_q p[b,q,k]/Z[b,q] ----------------
__global__ void colsum_k()
{
    int b = blockIdx.y;
    int k = blockIdx.x*256 + threadIdx.x;
    const float* p  = g_scores + (size_t)b*SEQ*SEQ + k;
    const float* iz = g_invZ + b*SEQ;
    float acc = 0.f;
    #pragma unroll 8
    for (int q=0; q<SEQ; q++)
        acc += p[(size_t)q*SEQ] * iz[q];
    g_wbar[b*SEQ + k] = acc;
}

// ---------------- final reduction ----------------
__global__ void final_acc_k(const float* __restrict__ x)
{
    int b = blockIdx.y, c = blockIdx.x;
    int d = threadIdx.x; // 512
    size_t base = ((size_t)b*SEQ + (size_t)c*128)*DIM + d;
    const float* wb = g_wbar + b*SEQ + c*128;
    float a = 0.f;
    #pragma unroll 4
    for (int s=0;s<128;s++)
        a += x[base + (size_t)s*DIM] + wb[s]*g_v[base + (size_t)s*DIM];
    g_part[(b*16+c)*DIM + d] = a;
}
__global__ void final_reduce_k(float* __restrict__ out)
{
    int b = blockIdx.x, d = threadIdx.x;
    float a = 0.f;
    #pragma unroll
    for (int c=0;c<16;c++) a += g_part[(b*16+c)*DIM + d];
    out[b*DIM + d] = a * (1.f/SEQ);
}

// ---------------- launch ----------------
extern "C" void kernel_launch(void* const* d_in, const int* in_sizes, int n_in,
                              void* d_out, int out_size)
{
    const float* x      = (const float*)d_in[0];
    const float* conv_w = (const float*)d_in[1];
    const float* conv_b = (const float*)d_in[2];
    const float* pre_g  = (const float*)d_in[3];
    const float* q_g    = (const float*)d_in[4];
    const float* k_g    = (const float*)d_in[5];
    const float* Wq     = (const float*)d_in[6];
    const float* Wk     = (const float*)d_in[7];
    const float* Wv     = (const float*)d_in[8];
    float* out = (float*)d_out;

    float *wc, *wqkv, *xconv, *xnorm, *qkv, *q, *k, *scores;
    cudaGetSymbolAddress((void**)&wc, g_wc);
    cudaGetSymbolAddress((void**)&wqkv, g_wqkv);
    cudaGetSymbolAddress((void**)&xconv, g_xconv);
    cudaGetSymbolAddress((void**)&xnorm, g_xnorm);
    cudaGetSymbolAddress((void**)&qkv, g_qkv);
    cudaGetSymbolAddress((void**)&q, g_q);
    cudaGetSymbolAddress((void**)&k, g_k);
    cudaGetSymbolAddress((void**)&scores, g_scores);

    cudaFuncSetAttribute(mma_gemm_k<0>, cudaFuncAttributeMaxDynamicSharedMemorySize, GSMEM);
    cudaFuncSetAttribute(mma_gemm_k<1>, cudaFuncAttributeMaxDynamicSharedMemorySize, GSMEM);
    cudaFuncSetAttribute(mma_gemm_k<2>, cudaFuncAttributeMaxDynamicSharedMemorySize, GSMEM);

    prep_weights<<<(3*DIM*DIM + 255)/256, 256>>>(conv_w, Wq, Wk, Wv);
    rope_tables_k<<<SEQ, HALF>>>();

    // conv: M=16384, N=512, K=1536
    mma_gemm_k<1><<<dim3(DIM/128, MR/128), 256, GSMEM>>>(x, wc, xconv, DIM, 3*DIM, conv_b, 1.f);
    rmsnorm_pre_k<<<MR, 128>>>(pre_g);

    // qkv: M=16384, N=1536, K=512
    mma_gemm_k<0><<<dim3(3*DIM/128, MR/128), 256, GSMEM>>>(xnorm, wqkv, qkv, 3*DIM, DIM, nullptr, 1.f);
    qkv_post_k<<<MR, 128>>>(q_g, k_g);

    // scores: per-batch NT, M=N=2048, K=512
    mma_gemm_k<2><<<dim3(SEQ/128, SEQ/128, BATCH), 256, GSMEM>>>(q, k, scores, SEQ, DIM,
                                                                 nullptr, 0.044194173824159216f);
    softmax_rows_k<<<MR, 256>>>();
    colsum_k<<<dim3(SEQ/256, BATCH), 256>>>();
    final_acc_k<<<dim3(16, BATCH), DIM>>>(x);
    final_reduce_k<<<BATCH, DIM>>>(out);
}

// round 4
// speedup vs baseline: 3.5544x; 2.3382x over previous
#include <cuda_runtime.h>
#include <cuda_fp16.h>
#include <cstdint>
#include <math.h>
#include <mma.h>

using namespace nvcuda;

#define BATCH 8
#define SEQ   2048
#define DIM   512
#define MR    (BATCH*SEQ)
#define HALF  (DIM/2)

// ---------------- static scratch ----------------
__device__ __half g_xh[(size_t)MR*DIM];        // x in fp16 (im2col source)
__device__ __half g_wch[3*DIM*DIM];            // conv weights: [dout=512][k=1536] K-major fp16
__device__ __half g_wqkvh[3*DIM*DIM];          // concat(Wq,Wk,Wv): [e=1536][d=512] K-major fp16
__device__ float  g_xconv[(size_t)MR*DIM];     // conv output f32 (pre-bias)
__device__ __half g_xnorm[(size_t)MR*DIM];     // rmsnorm(conv+bias) fp16
__device__ float  g_qkv[(size_t)MR*3*DIM];     // raw q|k|v f32
__device__ __half g_q[(size_t)MR*DIM];         // normed+rope'd q fp16
__device__ __half g_k[(size_t)MR*DIM];         // normed+rope'd k fp16
__device__ float  g_v[(size_t)MR*DIM];         // v f32
__device__ float  g_scores[(size_t)BATCH*SEQ*SEQ];
__device__ float  g_invZ[MR];
__device__ float  g_wbar[MR];
__device__ float  g_cos[SEQ*HALF];
__device__ float  g_sin[SEQ*HALF];
__device__ float  g_part[BATCH*16*DIM];

// ---------------- helpers ----------------
__device__ __forceinline__ uint32_t smem_u32(const void* p){
    uint32_t a;
    asm("{ .reg .u64 t; cvta.to.shared.u64 t, %1; cvt.u32.u64 %0, t; }" : "=r"(a) : "l"(p));
    return a;
}
__device__ __forceinline__ void cp_async16(uint32_t dst, const void* src, bool pred){
    int sz = pred ? 16 : 0;   // ZFILL when masked
    asm volatile("cp.async.cg.shared.global [%0], [%1], 16, %2;"
                 :: "r"(dst), "l"(src), "r"(sz));
}
__device__ __forceinline__ void cp_async_commit(){
    asm volatile("cp.async.commit_group;" ::: "memory");
}
template<int N>
__device__ __forceinline__ void cp_async_wait(){
    asm volatile("cp.async.wait_group %0;" :: "n"(N) : "memory");
}
__device__ __forceinline__ float warp_sum(float v){
    #pragma unroll
    for (int o=16;o;o>>=1) v += __shfl_xor_sync(0xffffffffu, v, o);
    return v;
}
__device__ __forceinline__ float warp_max(float v){
    #pragma unroll
    for (int o=16;o;o>>=1) v = fmaxf(v, __shfl_xor_sync(0xffffffffu, v, o));
    return v;
}
// FMA-pipe exp (avoids MUFU rt=8 bottleneck). |rel err| ~2e-5, valid for x <= 0-ish.
__device__ __forceinline__ float fast_exp(float x){
    float t = x * 1.4426950408889634f;   // log2(e)
    t = fmaxf(t, -125.0f);
    float fl = floorf(t);
    float f = t - fl;
    float p = 1.5403530e-4f;             // 2^f Taylor, degree 6
    p = fmaf(p, f, 1.3333558e-3f);
    p = fmaf(p, f, 9.6181291e-3f);
    p = fmaf(p, f, 5.5504109e-2f);
    p = fmaf(p, f, 2.4022651e-1f);
    p = fmaf(p, f, 6.9314718e-1f);
    p = fmaf(p, f, 1.0f);
    int i = (int)fl;
    return p * __int_as_float((i + 127) << 23);
}

// ---------------- input conversion / weight re-layout ----------------
__global__ void cvt_x_k(const float* __restrict__ x)
{
    size_t i = ((size_t)blockIdx.x*256 + threadIdx.x) * 4;
    float4 v = *(const float4*)&x[i];
    __half2 h0 = __floats2half2_rn(v.x, v.y);
    __half2 h1 = __floats2half2_rn(v.z, v.w);
    *(__half2*)&g_xh[i]   = h0;
    *(__half2*)&g_xh[i+2] = h1;
}

__global__ void prep_weights(const float* __restrict__ conv_w,
                             const float* __restrict__ Wq,
                             const float* __restrict__ Wk,
                             const float* __restrict__ Wv)
{
    int idx = blockIdx.x*256 + threadIdx.x;
    if (idx >= 3*DIM*DIM) return;
    {   // conv: [dout][kk], kk = t*512 + din
        int kk   = idx % (3*DIM);
        int dout = idx / (3*DIM);
        int din  = kk % DIM;
        int t    = kk / DIM;
        g_wch[idx] = __float2half_rn(conv_w[(dout*DIM + din)*3 + t]);
    }
    {   // qkv concat: [e_cat=1536][d=512]
        float w = (idx < DIM*DIM) ? Wq[idx]
                : (idx < 2*DIM*DIM) ? Wk[idx - DIM*DIM]
                : Wv[idx - 2*DIM*DIM];
        g_wqkvh[idx] = __float2half_rn(w);
    }
}

__global__ void rope_tables_k()
{
    int i = threadIdx.x;
    int s = blockIdx.x;
    double inv = pow(10000.0, -((double)(2*i)) / 512.0);
    double arg = (double)s * inv;
    g_cos[s*HALF + i] = (float)cos(arg);
    g_sin[s*HALF + i] = (float)sin(arg);
}

// ---------------- fp16 WMMA GEMM ----------------
// C[M,N] = A[M,K] * B[N,K]^T  (both K-major fp16), f32 accumulate.
// MODE 0: generic.  MODE 1: A = implicit im2col of g_xh (conv).  MODE 2: batched via z (scale on acc).
// Block 128x128x32, 8 warps (2x4), warp tile 64x32, wmma 16x16x16, 3-stage cp.async.
#define TLDH   40                    // padded leading dim (halfs)
#define STG_H  (2*128*TLDH)          // halfs per stage (A+B) = 10240
#define STG_B  (STG_H*2)             // bytes per stage = 20480
#define GSMEM  (3*STG_B)             // 61440

template<int MODE>
__global__ __launch_bounds__(256,2) void mma_gemm_k(
    const __half* __restrict__ Ah, const __half* __restrict__ Bh,
    float* __restrict__ C, int Nd, int Kd, float scale)
{
    extern __shared__ __half smh[];
    const uint32_t sb = smem_u32(smh);
    const int tid = threadIdx.x;
    const int wid = tid >> 5;
    const int wm = wid & 1, wn = wid >> 1;        // 2 x 4 warp grid
    const int bm = blockIdx.y*128, bn = blockIdx.x*128;
    if (MODE == 2) {
        size_t z = blockIdx.z;
        Ah += z * (size_t)SEQ * DIM;
        Bh += z * (size_t)SEQ * DIM;
        C  += z * (size_t)SEQ * SEQ;
    }

    wmma::fragment<wmma::accumulator,16,16,16,float> acc[4][2];
    #pragma unroll
    for (int i=0;i<4;i++)
        #pragma unroll
        for (int j=0;j<2;j++) wmma::fill_fragment(acc[i][j], 0.f);

    const int nIter = Kd / 32;

    auto load_tiles = [&](int it, int stg){
        const int k0 = it*32;
        const uint32_t abase = sb + stg*STG_B;
        const uint32_t bbase = abase + 128*TLDH*2;
        #pragma unroll
        for (int l=0;l<2;l++){
            int i   = l*256 + tid;        // 0..511
            int row = i >> 2;
            int kq  = (i & 3) * 8;        // half offset
            // A
            {
                const __half* src; bool pred = true;
                if (MODE == 1) {
                    int gm = bm + row;
                    int s  = gm & (SEQ-1);
                    int kg = k0 + kq;
                    int t  = kg >> 9;
                    pred = !((s==0 && t==0) || (s==SEQ-1 && t==2));
                    src = pred ? (Ah + (size_t)gm*DIM + kg - DIM) : Ah;
                } else {
                    src = Ah + (size_t)(bm+row)*Kd + k0 + kq;
                }
                cp_async16(abase + (row*TLDH + kq)*2, src, pred);
            }
            // B
            cp_async16(bbase + (row*TLDH + kq)*2,
                       Bh + (size_t)(bn+row)*Kd + k0 + kq, true);
        }
    };

    load_tiles(0, 0); cp_async_commit();
    load_tiles(1, 1); cp_async_commit();

    for (int it = 0; it < nIter; ++it) {
        cp_async_wait<1>();
        __syncthreads();
        const int stg = it % 3;
        const __half* Ab = smh + stg*STG_H;
        const __half* Bb = Ab + 128*TLDH;
        #pragma unroll
        for (int ks = 0; ks < 2; ks++) {
            wmma::fragment<wmma::matrix_b,16,16,16,__half,wmma::col_major> bf[2];
            #pragma unroll
            for (int j=0;j<2;j++)
                wmma::load_matrix_sync(bf[j], Bb + (wn*32 + j*16)*TLDH + ks*16, TLDH);
            #pragma unroll
            for (int i=0;i<4;i++){
                wmma::fragment<wmma::matrix_a,16,16,16,__half,wmma::row_major> af;
                wmma::load_matrix_sync(af, Ab + (wm*64 + i*16)*TLDH + ks*16, TLDH);
                wmma::mma_sync(acc[i][0], af, bf[0], acc[i][0]);
                wmma::mma_sync(acc[i][1], af, bf[1], acc[i][1]);
            }
        }
        if (it + 2 < nIter) load_tiles(it+2, (it+2)%3);
        cp_async_commit();
    }

    // epilogue: scale on fragments, direct global store
    #pragma unroll
    for (int i=0;i<4;i++)
        #pragma unroll
        for (int j=0;j<2;j++){
            if (MODE == 2) {
                #pragma unroll
                for (int e=0;e<acc[i][j].num_elements;e++) acc[i][j].x[e] *= scale;
            }
            wmma::store_matrix_sync(&C[(size_t)(bm + wm*64 + i*16)*Nd + bn + wn*32 + j*16],
                                    acc[i][j], Nd, wmma::mem_row_major);
        }
}

// ---------------- rmsnorm(conv + bias) -> fp16 ----------------
__global__ void rmsnorm_pre_k(const float* __restrict__ pre_g,
                              const float* __restrict__ conv_b)
{
    int m = blockIdx.x;
    int tid = threadIdx.x; // 128
    const float* row = g_xconv + (size_t)m*DIM;
    float4 v = *(const float4*)&row[tid*4];
    float4 b = *(const float4*)&conv_b[tid*4];
    v.x += b.x; v.y += b.y; v.z += b.z; v.w += b.w;
    float ss = v.x*v.x + v.y*v.y + v.z*v.z + v.w*v.w;
    ss = warp_sum(ss);
    __shared__ float smm[4];
    if ((tid&31)==0) smm[tid>>5] = ss;
    __syncthreads();
    float tot = smm[0]+smm[1]+smm[2]+smm[3];
    float r = rsqrtf(tot * (1.f/DIM) + 1e-6f);
    float4 g = *(const float4*)&pre_g[tid*4];
    __half2 o0 = __floats2half2_rn(v.x*r*g.x, v.y*r*g.y);
    __half2 o1 = __floats2half2_rn(v.z*r*g.z, v.w*r*g.w);
    *(__half2*)&g_xnorm[(size_t)m*DIM + tid*4]     = o0;
    *(__half2*)&g_xnorm[(size_t)m*DIM + tid*4 + 2] = o1;
}

// ---------------- rmsnorm + rope on q/k -> fp16, copy v f32 ----------------
__global__ void qkv_post_k(const float* __restrict__ q_g, const float* __restrict__ k_g)
{
    int m = blockIdx.x;
    int tid = threadIdx.x; // 128
    int s = m & (SEQ-1);
    const float* row = g_qkv + (size_t)m*3*DIM;
    float2 qa = *(const float2*)&row[2*tid];
    float2 qb = *(const float2*)&row[2*(tid+128)];
    float2 ka = *(const float2*)&row[DIM + 2*tid];
    float2 kb = *(const float2*)&row[DIM + 2*(tid+128)];
    float sq = qa.x*qa.x+qa.y*qa.y+qb.x*qb.x+qb.y*qb.y;
    float sk = ka.x*ka.x+ka.y*ka.y+kb.x*kb.x+kb.y*kb.y;
    sq = warp_sum(sq); sk = warp_sum(sk);
    __shared__ float smq[4], smk[4];
    if ((tid&31)==0) { smq[tid>>5]=sq; smk[tid>>5]=sk; }
    __syncthreads();
    float rq = rsqrtf((smq[0]+smq[1]+smq[2]+smq[3]) * (1.f/DIM) + 1e-6f);
    float rk = rsqrtf((smk[0]+smk[1]+smk[2]+smk[3]) * (1.f/DIM) + 1e-6f);

    #pragma unroll
    for (int pp=0; pp<2; pp++) {
        int p = tid + pp*128;
        float c  = g_cos[s*HALF + p];
        float sn = g_sin[s*HALF + p];
        float2 qv = pp ? qb : qa;
        float2 kv = pp ? kb : ka;
        float x0 = qv.x*rq*q_g[2*p], x1 = qv.y*rq*q_g[2*p+1];
        *(__half2*)&g_q[(size_t)m*DIM + 2*p] = __floats2half2_rn(x0*c - x1*sn, x0*sn + x1*c);
        float y0 = kv.x*rk*k_g[2*p], y1 = kv.y*rk*k_g[2*p+1];
        *(__half2*)&g_k[(size_t)m*DIM + 2*p] = __floats2half2_rn(y0*c - y1*sn, y0*sn + y1*c);
    }
    float4 vv = *(const float4*)&row[2*DIM + 4*tid];
    *(float4*)&g_v[(size_t)m*DIM + 4*tid] = vv;
}

// ---------------- softmax rows (fast exp) ----------------
__global__ void softmax_rows_k()
{
    int m = blockIdx.x;
    float* row = g_scores + (size_t)m*SEQ;
    int tid = threadIdx.x; // 256
    float v[8];
    float mx = -1e30f;
    #pragma unroll
    for (int c=0;c<8;c++) { v[c] = row[tid + c*256]; mx = fmaxf(mx, v[c]); }
    mx = warp_max(mx);
    __shared__ float sm1[8], sm2[8];
    if ((tid&31)==0) sm1[tid>>5]=mx;
    __syncthreads();
    mx = sm1[0];
    #pragma unroll
    for (int w=1;w<8;w++) mx = fmaxf(mx, sm1[w]);
    float ssum = 0.f;
    #pragma unroll
    for (int c=0;c<8;c++){ v[c] = fast_exp(v[c]-mx); ssum += v[c]; }
    ssum = warp_sum(ssum);
    if ((tid&31)==0) sm2[tid>>5]=ssum;
    __syncthreads();
    float Z = 0.f;
    #pragma unroll
    for (int w=0;w<8;w++) Z += sm2[w];
    #pragma unroll
    for (int c=0;c<8;c++) row[tid + c*256] = v[c];
    if (tid==0) g_invZ[m] = 1.f/Z;
}

// ---------------- wbar[b,k] = sum_q p[b,q,k]/Z[b,q] ----------------
__global__ void colsum_k()
{
    int b = blockIdx.y;
    int k = blockIdx.x*256 + threadIdx.x;
    const float* p  = g_scores + (size_t)b*SEQ*SEQ + k;
    const float* iz = g_invZ + b*SEQ;
    float acc = 0.f;
    #pragma unroll 8
    for (int q=0; q<SEQ; q++)
        acc += p[(size_t)q*SEQ] * iz[q];
    g_wbar[b*SEQ + k] = acc;
}

// ---------------- final reduction ----------------
__global__ void final_acc_k(const float* __restrict__ x)
{
    int b = blockIdx.y, c = blockIdx.x;
    int d = threadIdx.x; // 512
    size_t base = ((size_t)b*SEQ + (size_t)c*128)*DIM + d;
    const float* wb = g_wbar + b*SEQ + c*128;
    float a = 0.f;
    #pragma unroll 4
    for (int s=0;s<128;s++)
        a += x[base + (size_t)s*DIM] + wb[s]*g_v[base + (size_t)s*DIM];
    g_part[(b*16+c)*DIM + d] = a;
}
__global__ void final_reduce_k(float* __restrict__ out)
{
    int b = blockIdx.x, d = threadIdx.x;
    float a = 0.f;
    #pragma unroll
    for (int c=0;c<16;c++) a += g_part[(b*16+c)*DIM + d];
    out[b*DIM + d] = a * (1.f/SEQ);
}

// ---------------- launch ----------------
extern "C" void kernel_launch(void* const* d_in, const int* in_sizes, int n_in,
                              void* d_out, int out_size)
{
    const float* x      = (const float*)d_in[0];
    const float* conv_w = (const float*)d_in[1];
    const float* conv_b = (const float*)d_in[2];
    const float* pre_g  = (const float*)d_in[3];
    const float* q_g    = (const float*)d_in[4];
    const float* k_g    = (const float*)d_in[5];
    const float* Wq     = (const float*)d_in[6];
    const float* Wk     = (const float*)d_in[7];
    const float* Wv     = (const float*)d_in[8];
    float* out = (float*)d_out;

    __half *xh, *wch, *wqkvh, *xnorm, *q, *k;
    float *xconv, *qkv, *scores;
    cudaGetSymbolAddress((void**)&xh, g_xh);
    cudaGetSymbolAddress((void**)&wch, g_wch);
    cudaGetSymbolAddress((void**)&wqkvh, g_wqkvh);
    cudaGetSymbolAddress((void**)&xconv, g_xconv);
    cudaGetSymbolAddress((void**)&xnorm, g_xnorm);
    cudaGetSymbolAddress((void**)&qkv, g_qkv);
    cudaGetSymbolAddress((void**)&q, g_q);
    cudaGetSymbolAddress((void**)&k, g_k);
    cudaGetSymbolAddress((void**)&scores, g_scores);

    cudaFuncSetAttribute(mma_gemm_k<0>, cudaFuncAttributeMaxDynamicSharedMemorySize, GSMEM);
    cudaFuncSetAttribute(mma_gemm_k<1>, cudaFuncAttributeMaxDynamicSharedMemorySize, GSMEM);
    cudaFuncSetAttribute(mma_gemm_k<2>, cudaFuncAttributeMaxDynamicSharedMemorySize, GSMEM);

    cvt_x_k<<<MR*DIM/4/256, 256>>>(x);
    prep_weights<<<(3*DIM*DIM + 255)/256, 256>>>(conv_w, Wq, Wk, Wv);
    rope_tables_k<<<SEQ, HALF>>>();

    // conv: M=16384, N=512, K=1536
    mma_gemm_k<1><<<dim3(DIM/128, MR/128), 256, GSMEM>>>(xh, wch, xconv, DIM, 3*DIM, 1.f);
    rmsnorm_pre_k<<<MR, 128>>>(pre_g, conv_b);

    // qkv: M=16384, N=1536, K=512
    mma_gemm_k<0><<<dim3(3*DIM/128, MR/128), 256, GSMEM>>>(xnorm, wqkvh, qkv, 3*DIM, DIM, 1.f);
    qkv_post_k<<<MR, 128>>>(q_g, k_g);

    // scores: per-batch NT, M=N=2048, K=512
    mma_gemm_k<2><<<dim3(SEQ/128, SEQ/128, BATCH), 256, GSMEM>>>(q, k, scores, SEQ, DIM,
                                                                 0.044194173824159216f);
    softmax_rows_k<<<MR, 256>>>();
    colsum_k<<<dim3(SEQ/256, BATCH), 256>>>();
    final_acc_k<<<dim3(16, BATCH), DIM>>>(x);
    final_reduce_k<<<BATCH, DIM>>>(out);
}

// round 5
// speedup vs baseline: 3.6241x; 1.0196x over previous
#include <cuda_runtime.h>
#include <cuda_fp16.h>
#include <cstdint>
#include <math.h>
#include <mma.h>

using namespace nvcuda;

#define BATCH 8
#define SEQ   2048
#define DIM   512
#define MR    (BATCH*SEQ)
#define HALF  (DIM/2)

// ---------------- static scratch ----------------
__device__ __half g_xh[(size_t)MR*DIM];         // x fp16 (im2col source)
__device__ __half g_wch[3*DIM*DIM];             // conv weights [dout][k=1536] K-major fp16
__device__ __half g_wqkvh[3*DIM*DIM];           // concat(Wq,Wk,Wv) [e=1536][d=512] fp16
__device__ __half g_xconvh[(size_t)MR*DIM];     // conv output fp16 (pre-bias)
__device__ __half g_xnorm[(size_t)MR*DIM];      // rmsnorm(conv+bias) fp16
__device__ __half g_qkvh[(size_t)MR*3*DIM];     // raw q|k|v fp16
__device__ __half g_q[(size_t)MR*DIM];          // normed+rope'd q fp16
__device__ __half g_k[(size_t)MR*DIM];          // normed+rope'd k fp16
__device__ __half g_v[(size_t)MR*DIM];          // v fp16
__device__ float  g_scores[(size_t)BATCH*SEQ*SEQ];   // logits f32
__device__ __half g_p[(size_t)BATCH*SEQ*SEQ];        // softmax weights (p*invZ) fp16
__device__ float  g_wbar[MR];
__device__ float  g_cos[SEQ*HALF];
__device__ float  g_sin[SEQ*HALF];
__device__ float  g_part[BATCH*16*DIM];

// ---------------- helpers ----------------
__device__ __forceinline__ uint32_t smem_u32(const void* p){
    uint32_t a;
    asm("{ .reg .u64 t; cvta.to.shared.u64 t, %1; cvt.u32.u64 %0, t; }" : "=r"(a) : "l"(p));
    return a;
}
__device__ __forceinline__ void cp_async16(uint32_t dst, const void* src, bool pred){
    int sz = pred ? 16 : 0;   // ZFILL when masked
    asm volatile("cp.async.cg.shared.global [%0], [%1], 16, %2;"
                 :: "r"(dst), "l"(src), "r"(sz));
}
__device__ __forceinline__ void cp_async_commit(){
    asm volatile("cp.async.commit_group;" ::: "memory");
}
template<int N>
__device__ __forceinline__ void cp_async_wait(){
    asm volatile("cp.async.wait_group %0;" :: "n"(N) : "memory");
}
__device__ __forceinline__ float warp_sum(float v){
    #pragma unroll
    for (int o=16;o;o>>=1) v += __shfl_xor_sync(0xffffffffu, v, o);
    return v;
}
__device__ __forceinline__ float warp_max(float v){
    #pragma unroll
    for (int o=16;o;o>>=1) v = fmaxf(v, __shfl_xor_sync(0xffffffffu, v, o));
    return v;
}
// FMA-pipe exp. |rel err| ~2e-5.
__device__ __forceinline__ float fast_exp(float x){
    float t = x * 1.4426950408889634f;
    t = fmaxf(t, -125.0f);
    float fl = floorf(t);
    float f = t - fl;
    float p = 1.5403530e-4f;
    p = fmaf(p, f, 1.3333558e-3f);
    p = fmaf(p, f, 9.6181291e-3f);
    p = fmaf(p, f, 5.5504109e-2f);
    p = fmaf(p, f, 2.4022651e-1f);
    p = fmaf(p, f, 6.9314718e-1f);
    p = fmaf(p, f, 1.0f);
    int i = (int)fl;
    return p * __int_as_float((i + 127) << 23);
}

// ---------------- input conversion / weight re-layout ----------------
__global__ void cvt_x_k(const float* __restrict__ x)
{
    size_t i = ((size_t)blockIdx.x*256 + threadIdx.x) * 8;
    float4 v0 = *(const float4*)&x[i];
    float4 v1 = *(const float4*)&x[i+4];
    __half2 h[4] = { __floats2half2_rn(v0.x,v0.y), __floats2half2_rn(v0.z,v0.w),
                     __floats2half2_rn(v1.x,v1.y), __floats2half2_rn(v1.z,v1.w) };
    *(uint4*)&g_xh[i] = *(uint4*)h;
}

__global__ void prep_weights(const float* __restrict__ conv_w,
                             const float* __restrict__ Wq,
                             const float* __restrict__ Wk,
                             const float* __restrict__ Wv)
{
    int idx = blockIdx.x*256 + threadIdx.x;
    if (idx >= 3*DIM*DIM) return;
    {   // conv: [dout][kk], kk = t*512 + din
        int kk   = idx % (3*DIM);
        int dout = idx / (3*DIM);
        int din  = kk % DIM;
        int t    = kk / DIM;
        g_wch[idx] = __float2half_rn(conv_w[(dout*DIM + din)*3 + t]);
    }
    {   // qkv concat
        float w = (idx < DIM*DIM) ? Wq[idx]
                : (idx < 2*DIM*DIM) ? Wk[idx - DIM*DIM]
                : Wv[idx - 2*DIM*DIM];
        g_wqkvh[idx] = __float2half_rn(w);
    }
}

__global__ void rope_tables_k()
{
    int i = threadIdx.x;
    int s = blockIdx.x;
    double inv = pow(10000.0, -((double)(2*i)) / 512.0);
    double arg = (double)s * inv;
    g_cos[s*HALF + i] = (float)cos(arg);
    g_sin[s*HALF + i] = (float)sin(arg);
}

// ---------------- fp16 WMMA GEMM ----------------
// C[M,N] = A[M,K] * B[N,K]^T, f32 accumulate.
// MODE 0: generic, C=fp16.  MODE 1: A = implicit im2col (conv), C=fp16.  MODE 2: batched, C=f32*scale.
#define TLDH   40
#define STG_H  (2*128*TLDH)          // halfs per stage = 10240
#define STG_B  (STG_H*2)             // bytes per stage = 20480
#define ELD    132                   // epilogue f32 tile leading dim
#define GSMEM  (128*ELD*4)           // 67584 >= 3*STG_B (61440)

template<int MODE>
__global__ __launch_bounds__(256,2) void mma_gemm_k(
    const __half* __restrict__ Ah, const __half* __restrict__ Bh,
    void* __restrict__ Cv, int Nd, int Kd, float scale)
{
    extern __shared__ __half smh[];
    const uint32_t sb = smem_u32(smh);
    const int tid = threadIdx.x;
    const int wid = tid >> 5;
    const int wm = wid & 1, wn = wid >> 1;
    const int bm = blockIdx.y*128, bn = blockIdx.x*128;
    float* Cf = (float*)Cv;
    __half* Ch = (__half*)Cv;
    if (MODE == 2) {
        size_t z = blockIdx.z;
        Ah += z * (size_t)SEQ * DIM;
        Bh += z * (size_t)SEQ * DIM;
        Cf += z * (size_t)SEQ * SEQ;
    }

    wmma::fragment<wmma::accumulator,16,16,16,float> acc[4][2];
    #pragma unroll
    for (int i=0;i<4;i++)
        #pragma unroll
        for (int j=0;j<2;j++) wmma::fill_fragment(acc[i][j], 0.f);

    const int nIter = Kd / 32;

    auto load_tiles = [&](int it, int stg){
        const int k0 = it*32;
        const uint32_t abase = sb + stg*STG_B;
        const uint32_t bbase = abase + 128*TLDH*2;
        #pragma unroll
        for (int l=0;l<2;l++){
            int i   = l*256 + tid;
            int row = i >> 2;
            int kq  = (i & 3) * 8;
            {
                const __half* src; bool pred = true;
                if (MODE == 1) {
                    int gm = bm + row;
                    int s  = gm & (SEQ-1);
                    int kg = k0 + kq;
                    int t  = kg >> 9;
                    pred = !((s==0 && t==0) || (s==SEQ-1 && t==2));
                    src = pred ? (Ah + (size_t)gm*DIM + kg - DIM) : Ah;
                } else {
                    src = Ah + (size_t)(bm+row)*Kd + k0 + kq;
                }
                cp_async16(abase + (row*TLDH + kq)*2, src, pred);
            }
            cp_async16(bbase + (row*TLDH + kq)*2,
                       Bh + (size_t)(bn+row)*Kd + k0 + kq, true);
        }
    };

    load_tiles(0, 0); cp_async_commit();
    load_tiles(1, 1); cp_async_commit();

    for (int it = 0; it < nIter; ++it) {
        cp_async_wait<1>();
        __syncthreads();
        const int stg = it % 3;
        const __half* Ab = smh + stg*STG_H;
        const __half* Bb = Ab + 128*TLDH;
        #pragma unroll
        for (int ks = 0; ks < 2; ks++) {
            wmma::fragment<wmma::matrix_b,16,16,16,__half,wmma::col_major> bf[2];
            #pragma unroll
            for (int j=0;j<2;j++)
                wmma::load_matrix_sync(bf[j], Bb + (wn*32 + j*16)*TLDH + ks*16, TLDH);
            #pragma unroll
            for (int i=0;i<4;i++){
                wmma::fragment<wmma::matrix_a,16,16,16,__half,wmma::row_major> af;
                wmma::load_matrix_sync(af, Ab + (wm*64 + i*16)*TLDH + ks*16, TLDH);
                wmma::mma_sync(acc[i][0], af, bf[0], acc[i][0]);
                wmma::mma_sync(acc[i][1], af, bf[1], acc[i][1]);
            }
        }
        if (it + 2 < nIter) load_tiles(it+2, (it+2)%3);
        cp_async_commit();
    }

    if (MODE == 2) {
        #pragma unroll
        for (int i=0;i<4;i++)
            #pragma unroll
            for (int j=0;j<2;j++){
                #pragma unroll
                for (int e=0;e<acc[i][j].num_elements;e++) acc[i][j].x[e] *= scale;
                wmma::store_matrix_sync(&Cf[(size_t)(bm + wm*64 + i*16)*Nd + bn + wn*32 + j*16],
                                        acc[i][j], Nd, wmma::mem_row_major);
            }
    } else {
        // fp16 C via block smem tile
        cp_async_wait<0>();
        __syncthreads();                      // stage smem no longer needed
        float* eb = (float*)smh;
        #pragma unroll
        for (int i=0;i<4;i++)
            #pragma unroll
            for (int j=0;j<2;j++)
                wmma::store_matrix_sync(eb + (wm*64 + i*16)*ELD + wn*32 + j*16,
                                        acc[i][j], ELD, wmma::mem_row_major);
        __syncthreads();
        #pragma unroll
        for (int p=0;p<8;p++){
            int e = p*256 + tid;              // 0..2047 chunks of 8
            int row = e >> 4;
            int c0 = (e & 15) * 8;
            float4 a = *(float4*)&eb[row*ELD + c0];
            float4 b = *(float4*)&eb[row*ELD + c0 + 4];
            __half2 h[4] = { __floats2half2_rn(a.x,a.y), __floats2half2_rn(a.z,a.w),
                             __floats2half2_rn(b.x,b.y), __floats2half2_rn(b.z,b.w) };
            *(uint4*)&Ch[(size_t)(bm+row)*Nd + bn + c0] = *(uint4*)h;
        }
    }
}

// ---------------- rmsnorm(conv + bias) -> fp16, warp per row ----------------
__global__ void rmsnorm_pre_k(const float* __restrict__ pre_g,
                              const float* __restrict__ conv_b)
{
    int row  = blockIdx.x*8 + (threadIdx.x >> 5);
    int lane = threadIdx.x & 31;
    const __half* r = g_xconvh + (size_t)row*DIM + lane*16;
    uint4 u0 = *(const uint4*)r;
    uint4 u1 = *(const uint4*)(r + 8);
    float4 b0 = *(const float4*)&conv_b[lane*16];
    float4 b1 = *(const float4*)&conv_b[lane*16+4];
    float4 b2 = *(const float4*)&conv_b[lane*16+8];
    float4 b3 = *(const float4*)&conv_b[lane*16+12];
    __half2* h0 = (__half2*)&u0;
    __half2* h1 = (__half2*)&u1;
    float v[16];
    #pragma unroll
    for (int i=0;i<4;i++){
        float2 f = __half22float2(h0[i]); v[2*i]=f.x; v[2*i+1]=f.y;
        float2 g = __half22float2(h1[i]); v[8+2*i]=g.x; v[8+2*i+1]=g.y;
    }
    const float* bb = &b0.x;   // contiguous float4s
    float bias[16] = {b0.x,b0.y,b0.z,b0.w,b1.x,b1.y,b1.z,b1.w,
                      b2.x,b2.y,b2.z,b2.w,b3.x,b3.y,b3.z,b3.w};
    (void)bb;
    float ss = 0.f;
    #pragma unroll
    for (int i=0;i<16;i++){ v[i] += bias[i]; ss += v[i]*v[i]; }
    ss = warp_sum(ss);
    float rr = rsqrtf(ss * (1.f/DIM) + 1e-6f);
    float4 g0 = *(const float4*)&pre_g[lane*16];
    float4 g1 = *(const float4*)&pre_g[lane*16+4];
    float4 g2 = *(const float4*)&pre_g[lane*16+8];
    float4 g3 = *(const float4*)&pre_g[lane*16+12];
    float gg[16] = {g0.x,g0.y,g0.z,g0.w,g1.x,g1.y,g1.z,g1.w,
                    g2.x,g2.y,g2.z,g2.w,g3.x,g3.y,g3.z,g3.w};
    __half2 o[8];
    #pragma unroll
    for (int i=0;i<8;i++)
        o[i] = __floats2half2_rn(v[2*i]*rr*gg[2*i], v[2*i+1]*rr*gg[2*i+1]);
    __half* w = g_xnorm + (size_t)row*DIM + lane*16;
    *(uint4*)w       = *(uint4*)&o[0];
    *(uint4*)(w + 8) = *(uint4*)&o[4];
}

// ---------------- rmsnorm + rope on q/k -> fp16, v passthrough; warp per row ----------------
__global__ void qkv_post_k(const float* __restrict__ q_g, const float* __restrict__ k_g)
{
    int row  = blockIdx.x*8 + (threadIdx.x >> 5);
    int lane = threadIdx.x & 31;
    int s = row & (SEQ-1);
    const __half* r = g_qkvh + (size_t)row*3*DIM + lane*16;
    uint4 q0 = *(const uint4*)r;
    uint4 q1 = *(const uint4*)(r + 8);
    uint4 k0 = *(const uint4*)(r + DIM);
    uint4 k1 = *(const uint4*)(r + DIM + 8);
    uint4 v0 = *(const uint4*)(r + 2*DIM);
    uint4 v1 = *(const uint4*)(r + 2*DIM + 8);
    float q[16], k[16];
    {
        __half2* hq0=(__half2*)&q0; __half2* hq1=(__half2*)&q1;
        __half2* hk0=(__half2*)&k0; __half2* hk1=(__half2*)&k1;
        #pragma unroll
        for (int i=0;i<4;i++){
            float2 f;
            f=__half22float2(hq0[i]); q[2*i]=f.x; q[2*i+1]=f.y;
            f=__half22float2(hq1[i]); q[8+2*i]=f.x; q[8+2*i+1]=f.y;
            f=__half22float2(hk0[i]); k[2*i]=f.x; k[2*i+1]=f.y;
            f=__half22float2(hk1[i]); k[8+2*i]=f.x; k[8+2*i+1]=f.y;
        }
    }
    float sq=0.f, sk=0.f;
    #pragma unroll
    for (int i=0;i<16;i++){ sq += q[i]*q[i]; sk += k[i]*k[i]; }
    sq = warp_sum(sq); sk = warp_sum(sk);
    float rq = rsqrtf(sq * (1.f/DIM) + 1e-6f);
    float rk = rsqrtf(sk * (1.f/DIM) + 1e-6f);

    float4 c0 = *(const float4*)&g_cos[s*HALF + lane*8];
    float4 c1 = *(const float4*)&g_cos[s*HALF + lane*8 + 4];
    float4 s0 = *(const float4*)&g_sin[s*HALF + lane*8];
    float4 s1 = *(const float4*)&g_sin[s*HALF + lane*8 + 4];
    float cs[8] = {c0.x,c0.y,c0.z,c0.w,c1.x,c1.y,c1.z,c1.w};
    float sn[8] = {s0.x,s0.y,s0.z,s0.w,s1.x,s1.y,s1.z,s1.w};
    float4 qg0 = *(const float4*)&q_g[lane*16];
    float4 qg1 = *(const float4*)&q_g[lane*16+4];
    float4 qg2 = *(const float4*)&q_g[lane*16+8];
    float4 qg3 = *(const float4*)&q_g[lane*16+12];
    float4 kg0 = *(const float4*)&k_g[lane*16];
    float4 kg1 = *(const float4*)&k_g[lane*16+4];
    float4 kg2 = *(const float4*)&k_g[lane*16+8];
    float4 kg3 = *(const float4*)&k_g[lane*16+12];
    float qg[16] = {qg0.x,qg0.y,qg0.z,qg0.w,qg1.x,qg1.y,qg1.z,qg1.w,
                    qg2.x,qg2.y,qg2.z,qg2.w,qg3.x,qg3.y,qg3.z,qg3.w};
    float kg[16] = {kg0.x,kg0.y,kg0.z,kg0.w,kg1.x,kg1.y,kg1.z,kg1.w,
                    kg2.x,kg2.y,kg2.z,kg2.w,kg3.x,kg3.y,kg3.z,kg3.w};

    __half2 qo[8], ko[8];
    #pragma unroll
    for (int j=0;j<8;j++){
        float x0 = q[2*j]*rq*qg[2*j], x1 = q[2*j+1]*rq*qg[2*j+1];
        qo[j] = __floats2half2_rn(x0*cs[j] - x1*sn[j], x0*sn[j] + x1*cs[j]);
        float y0 = k[2*j]*rk*kg[2*j], y1 = k[2*j+1]*rk*kg[2*j+1];
        ko[j] = __floats2half2_rn(y0*cs[j] - y1*sn[j], y0*sn[j] + y1*cs[j]);
    }
    __half* wq = g_q + (size_t)row*DIM + lane*16;
    __half* wk = g_k + (size_t)row*DIM + lane*16;
    __half* wv = g_v + (size_t)row*DIM + lane*16;
    *(uint4*)wq = *(uint4*)&qo[0];  *(uint4*)(wq+8) = *(uint4*)&qo[4];
    *(uint4*)wk = *(uint4*)&ko[0];  *(uint4*)(wk+8) = *(uint4*)&ko[4];
    *(uint4*)wv = v0;               *(uint4*)(wv+8) = v1;
}

// ---------------- softmax rows: f32 logits -> fp16 (p * invZ) ----------------
__global__ void softmax_rows_k()
{
    int m = blockIdx.x;
    const float* row = g_scores + (size_t)m*SEQ;
    int tid = threadIdx.x; // 256
    int c0 = tid*8;
    float4 a = *(const float4*)&row[c0];
    float4 b = *(const float4*)&row[c0+4];
    float v[8] = {a.x,a.y,a.z,a.w,b.x,b.y,b.z,b.w};
    float mx = v[0];
    #pragma unroll
    for (int c=1;c<8;c++) mx = fmaxf(mx, v[c]);
    mx = warp_max(mx);
    __shared__ float sm1[8], sm2[8];
    if ((tid&31)==0) sm1[tid>>5]=mx;
    __syncthreads();
    mx = sm1[0];
    #pragma unroll
    for (int w=1;w<8;w++) mx = fmaxf(mx, sm1[w]);
    float ssum = 0.f;
    #pragma unroll
    for (int c=0;c<8;c++){ v[c] = fast_exp(v[c]-mx); ssum += v[c]; }
    ssum = warp_sum(ssum);
    if ((tid&31)==0) sm2[tid>>5]=ssum;
    __syncthreads();
    float Z = 0.f;
    #pragma unroll
    for (int w=0;w<8;w++) Z += sm2[w];
    float iz = 1.f / Z;
    __half2 o[4];
    #pragma unroll
    for (int j=0;j<4;j++)
        o[j] = __floats2half2_rn(v[2*j]*iz, v[2*j+1]*iz);
    *(uint4*)&g_p[(size_t)m*SEQ + c0] = *(uint4*)o;
}

// ---------------- wbar[b,k] = sum_q p[b,q,k] ----------------
__global__ void colsum_k()
{
    int b = blockIdx.y;
    int k2 = blockIdx.x*256 + threadIdx.x;   // half2 column index
    const __half2* p = (const __half2*)(g_p + (size_t)b*SEQ*SEQ) + k2;
    float ax = 0.f, ay = 0.f;
    #pragma unroll 8
    for (int q=0; q<SEQ; q++){
        float2 f = __half22float2(p[(size_t)q*(SEQ/2)]);
        ax += f.x; ay += f.y;
    }
    g_wbar[b*SEQ + 2*k2]     = ax;
    g_wbar[b*SEQ + 2*k2 + 1] = ay;
}

// ---------------- final reduction ----------------
__global__ void final_acc_k(const float* __restrict__ x)
{
    int b = blockIdx.y, c = blockIdx.x;
    int d = threadIdx.x; // 512
    size_t base = ((size_t)b*SEQ + (size_t)c*128)*DIM + d;
    const float* wb = g_wbar + b*SEQ + c*128;
    float a = 0.f;
    #pragma unroll 4
    for (int s=0;s<128;s++)
        a += x[base + (size_t)s*DIM] + wb[s]*__half2float(g_v[base + (size_t)s*DIM]);
    g_part[(b*16+c)*DIM + d] = a;
}
__global__ void final_reduce_k(float* __restrict__ out)
{
    int b = blockIdx.x, d = threadIdx.x;
    float a = 0.f;
    #pragma unroll
    for (int c=0;c<16;c++) a += g_part[(b*16+c)*DIM + d];
    out[b*DIM + d] = a * (1.f/SEQ);
}

// ---------------- launch ----------------
extern "C" void kernel_launch(void* const* d_in, const int* in_sizes, int n_in,
                              void* d_out, int out_size)
{
    const float* x      = (const float*)d_in[0];
    const float* conv_w = (const float*)d_in[1];
    const float* conv_b = (const float*)d_in[2];
    const float* pre_g  = (const float*)d_in[3];
    const float* q_g    = (const float*)d_in[4];
    const float* k_g    = (const float*)d_in[5];
    const float* Wq     = (const float*)d_in[6];
    const float* Wk     = (const float*)d_in[7];
    const float* Wv     = (const float*)d_in[8];
    float* out = (float*)d_out;

    __half *xh, *wch, *wqkvh, *xconvh, *xnorm, *qkvh, *q, *k;
    float *scores;
    cudaGetSymbolAddress((void**)&xh, g_xh);
    cudaGetSymbolAddress((void**)&wch, g_wch);
    cudaGetSymbolAddress((void**)&wqkvh, g_wqkvh);
    cudaGetSymbolAddress((void**)&xconvh, g_xconvh);
    cudaGetSymbolAddress((void**)&xnorm, g_xnorm);
    cudaGetSymbolAddress((void**)&qkvh, g_qkvh);
    cudaGetSymbolAddress((void**)&q, g_q);
    cudaGetSymbolAddress((void**)&k, g_k);
    cudaGetSymbolAddress((void**)&scores, g_scores);

    cudaFuncSetAttribute(mma_gemm_k<0>, cudaFuncAttributeMaxDynamicSharedMemorySize, GSMEM);
    cudaFuncSetAttribute(mma_gemm_k<1>, cudaFuncAttributeMaxDynamicSharedMemorySize, GSMEM);
    cudaFuncSetAttribute(mma_gemm_k<2>, cudaFuncAttributeMaxDynamicSharedMemorySize, GSMEM);

    cvt_x_k<<<MR*DIM/8/256, 256>>>(x);
    prep_weights<<<(3*DIM*DIM + 255)/256, 256>>>(conv_w, Wq, Wk, Wv);
    rope_tables_k<<<SEQ, HALF>>>();

    // conv: M=16384, N=512, K=1536, C fp16
    mma_gemm_k<1><<<dim3(DIM/128, MR/128), 256, GSMEM>>>(xh, wch, xconvh, DIM, 3*DIM, 1.f);
    rmsnorm_pre_k<<<MR/8, 256>>>(pre_g, conv_b);

    // qkv: M=16384, N=1536, K=512, C fp16
    mma_gemm_k<0><<<dim3(3*DIM/128, MR/128), 256, GSMEM>>>(xnorm, wqkvh, qkvh, 3*DIM, DIM, 1.f);
    qkv_post_k<<<MR/8, 256>>>(q_g, k_g);

    // scores: per-batch NT, M=N=2048, K=512, C f32
    mma_gemm_k<2><<<dim3(SEQ/128, SEQ/128, BATCH), 256, GSMEM>>>(q, k, scores, SEQ, DIM,
                                                                 0.044194173824159216f);
    softmax_rows_k<<<MR, 256>>>();
    colsum_k<<<dim3(SEQ/2/256, BATCH), 256>>>();
    final_acc_k<<<dim3(16, BATCH), DIM>>>(x);
    final_reduce_k<<<BATCH, DIM>>>(out);
}

// round 6
// speedup vs baseline: 4.6468x; 1.2822x over previous
#include <cuda_runtime.h>
#include <cuda_fp16.h>
#include <cstdint>
#include <math.h>
#include <mma.h>

using namespace nvcuda;

#define BATCH 8
#define SEQ   2048
#define DIM   512
#define MR    (BATCH*SEQ)
#define HALF  (DIM/2)

// ---------------- static scratch ----------------
__device__ __half g_xh[(size_t)MR*DIM];         // x fp16 (im2col source + final acc)
__device__ __half g_wch[3*DIM*DIM];             // conv weights [dout][k=1536] K-major fp16
__device__ __half g_wqkvh[3*DIM*DIM];           // concat(Wq,Wk,Wv) [e=1536][d=512] fp16
__device__ __half g_xconvh[(size_t)MR*DIM];     // conv output fp16 (pre-bias)
__device__ __half g_xnorm[(size_t)MR*DIM];      // rmsnorm(conv+bias) fp16
__device__ __half g_qkvh[(size_t)MR*3*DIM];     // raw q|k|v fp16
__device__ __half g_q[(size_t)MR*DIM];          // normed+rope'd q fp16
__device__ __half g_k[(size_t)MR*DIM];          // normed+rope'd k fp16
__device__ __half g_v[(size_t)MR*DIM];          // v fp16
__device__ __half g_scoresh[(size_t)BATCH*SEQ*SEQ];  // logits fp16 (bounded |s|<=22.7)
__device__ float  g_wbar[MR];
__device__ float  g_cos[SEQ*HALF];
__device__ float  g_sin[SEQ*HALF];
__device__ float  g_part[BATCH*16*DIM];

// ---------------- helpers ----------------
__device__ __forceinline__ uint32_t smem_u32(const void* p){
    uint32_t a;
    asm("{ .reg .u64 t; cvta.to.shared.u64 t, %1; cvt.u32.u64 %0, t; }" : "=r"(a) : "l"(p));
    return a;
}
__device__ __forceinline__ void cp_async16(uint32_t dst, const void* src, bool pred){
    int sz = pred ? 16 : 0;   // ZFILL when masked
    asm volatile("cp.async.cg.shared.global [%0], [%1], 16, %2;"
                 :: "r"(dst), "l"(src), "r"(sz));
}
__device__ __forceinline__ void cp_async_commit(){
    asm volatile("cp.async.commit_group;" ::: "memory");
}
template<int N>
__device__ __forceinline__ void cp_async_wait(){
    asm volatile("cp.async.wait_group %0;" :: "n"(N) : "memory");
}
__device__ __forceinline__ float warp_sum(float v){
    #pragma unroll
    for (int o=16;o;o>>=1) v += __shfl_xor_sync(0xffffffffu, v, o);
    return v;
}
// FMA-pipe exp. |rel err| ~2e-5. Valid for arg in [-87, 60]; here [-46, 23].
__device__ __forceinline__ float fast_exp(float x){
    float t = x * 1.4426950408889634f;
    t = fmaxf(t, -125.0f);
    float fl = floorf(t);
    float f = t - fl;
    float p = 1.5403530e-4f;
    p = fmaf(p, f, 1.3333558e-3f);
    p = fmaf(p, f, 9.6181291e-3f);
    p = fmaf(p, f, 5.5504109e-2f);
    p = fmaf(p, f, 2.4022651e-1f);
    p = fmaf(p, f, 6.9314718e-1f);
    p = fmaf(p, f, 1.0f);
    int i = (int)fl;
    return p * __int_as_float((i + 127) << 23);
}

// ---------------- input conversion / weight re-layout ----------------
__global__ void cvt_x_k(const float* __restrict__ x)
{
    size_t i = ((size_t)blockIdx.x*256 + threadIdx.x) * 8;
    float4 v0 = *(const float4*)&x[i];
    float4 v1 = *(const float4*)&x[i+4];
    __half2 h[4] = { __floats2half2_rn(v0.x,v0.y), __floats2half2_rn(v0.z,v0.w),
                     __floats2half2_rn(v1.x,v1.y), __floats2half2_rn(v1.z,v1.w) };
    *(uint4*)&g_xh[i] = *(uint4*)h;
}

__global__ void prep_weights(const float* __restrict__ conv_w,
                             const float* __restrict__ Wq,
                             const float* __restrict__ Wk,
                             const float* __restrict__ Wv)
{
    int idx = blockIdx.x*256 + threadIdx.x;
    if (idx >= 3*DIM*DIM) return;
    {   // conv: [dout][kk], kk = t*512 + din
        int kk   = idx % (3*DIM);
        int dout = idx / (3*DIM);
        int din  = kk % DIM;
        int t    = kk / DIM;
        g_wch[idx] = __float2half_rn(conv_w[(dout*DIM + din)*3 + t]);
    }
    {   // qkv concat
        float w = (idx < DIM*DIM) ? Wq[idx]
                : (idx < 2*DIM*DIM) ? Wk[idx - DIM*DIM]
                : Wv[idx - 2*DIM*DIM];
        g_wqkvh[idx] = __float2half_rn(w);
    }
}

__global__ void rope_tables_k()
{
    int i = threadIdx.x;
    int s = blockIdx.x;
    double inv = pow(10000.0, -((double)(2*i)) / 512.0);
    double arg = (double)s * inv;
    g_cos[s*HALF + i] = (float)cos(arg);
    g_sin[s*HALF + i] = (float)sin(arg);
}

__global__ void zero_wbar_k(){ g_wbar[blockIdx.x*256 + threadIdx.x] = 0.f; }

// ---------------- fp16 WMMA GEMM ----------------
// C[M,N] = A[M,K] * B[N,K]^T, f32 accumulate, fp16 C.
// MODE 0: generic.  MODE 1: A = implicit im2col (conv).  MODE 2: batched via z, scale on acc.
#define TLDH   40
#define STG_H  (2*128*TLDH)          // halfs per stage = 10240
#define STG_B  (STG_H*2)             // bytes per stage = 20480
#define ELD    132                   // epilogue f32 tile leading dim
#define GSMEM  (128*ELD*4)           // 67584 >= 3*STG_B (61440)

template<int MODE>
__global__ __launch_bounds__(256,2) void mma_gemm_k(
    const __half* __restrict__ Ah, const __half* __restrict__ Bh,
    __half* __restrict__ Ch, int Nd, int Kd, float scale)
{
    extern __shared__ __half smh[];
    const uint32_t sb = smem_u32(smh);
    const int tid = threadIdx.x;
    const int wid = tid >> 5;
    const int wm = wid & 1, wn = wid >> 1;
    const int bm = blockIdx.y*128, bn = blockIdx.x*128;
    if (MODE == 2) {
        size_t z = blockIdx.z;
        Ah += z * (size_t)SEQ * DIM;
        Bh += z * (size_t)SEQ * DIM;
        Ch += z * (size_t)SEQ * SEQ;
    }

    wmma::fragment<wmma::accumulator,16,16,16,float> acc[4][2];
    #pragma unroll
    for (int i=0;i<4;i++)
        #pragma unroll
        for (int j=0;j<2;j++) wmma::fill_fragment(acc[i][j], 0.f);

    const int nIter = Kd / 32;

    auto load_tiles = [&](int it, int stg){
        const int k0 = it*32;
        const uint32_t abase = sb + stg*STG_B;
        const uint32_t bbase = abase + 128*TLDH*2;
        #pragma unroll
        for (int l=0;l<2;l++){
            int i   = l*256 + tid;
            int row = i >> 2;
            int kq  = (i & 3) * 8;
            {
                const __half* src; bool pred = true;
                if (MODE == 1) {
                    int gm = bm + row;
                    int s  = gm & (SEQ-1);
                    int kg = k0 + kq;
                    int t  = kg >> 9;
                    pred = !((s==0 && t==0) || (s==SEQ-1 && t==2));
                    src = pred ? (Ah + (size_t)gm*DIM + kg - DIM) : Ah;
                } else {
                    src = Ah + (size_t)(bm+row)*Kd + k0 + kq;
                }
                cp_async16(abase + (row*TLDH + kq)*2, src, pred);
            }
            cp_async16(bbase + (row*TLDH + kq)*2,
                       Bh + (size_t)(bn+row)*Kd + k0 + kq, true);
        }
    };

    load_tiles(0, 0); cp_async_commit();
    load_tiles(1, 1); cp_async_commit();

    for (int it = 0; it < nIter; ++it) {
        cp_async_wait<1>();
        __syncthreads();
        const int stg = it % 3;
        const __half* Ab = smh + stg*STG_H;
        const __half* Bb = Ab + 128*TLDH;
        #pragma unroll
        for (int ks = 0; ks < 2; ks++) {
            wmma::fragment<wmma::matrix_b,16,16,16,__half,wmma::col_major> bf[2];
            #pragma unroll
            for (int j=0;j<2;j++)
                wmma::load_matrix_sync(bf[j], Bb + (wn*32 + j*16)*TLDH + ks*16, TLDH);
            #pragma unroll
            for (int i=0;i<4;i++){
                wmma::fragment<wmma::matrix_a,16,16,16,__half,wmma::row_major> af;
                wmma::load_matrix_sync(af, Ab + (wm*64 + i*16)*TLDH + ks*16, TLDH);
                wmma::mma_sync(acc[i][0], af, bf[0], acc[i][0]);
                wmma::mma_sync(acc[i][1], af, bf[1], acc[i][1]);
            }
        }
        if (it + 2 < nIter) load_tiles(it+2, (it+2)%3);
        cp_async_commit();
    }

    // fp16 C via block smem tile (all modes)
    cp_async_wait<0>();
    __syncthreads();
    float* eb = (float*)smh;
    #pragma unroll
    for (int i=0;i<4;i++)
        #pragma unroll
        for (int j=0;j<2;j++){
            if (MODE == 2) {
                #pragma unroll
                for (int e=0;e<acc[i][j].num_elements;e++) acc[i][j].x[e] *= scale;
            }
            wmma::store_matrix_sync(eb + (wm*64 + i*16)*ELD + wn*32 + j*16,
                                    acc[i][j], ELD, wmma::mem_row_major);
        }
    __syncthreads();
    #pragma unroll
    for (int p=0;p<8;p++){
        int e = p*256 + tid;              // 0..2047 chunks of 8
        int row = e >> 4;
        int c0 = (e & 15) * 8;
        float4 a = *(float4*)&eb[row*ELD + c0];
        float4 b = *(float4*)&eb[row*ELD + c0 + 4];
        __half2 h[4] = { __floats2half2_rn(a.x,a.y), __floats2half2_rn(a.z,a.w),
                         __floats2half2_rn(b.x,b.y), __floats2half2_rn(b.z,b.w) };
        *(uint4*)&Ch[(size_t)(bm+row)*Nd + bn + c0] = *(uint4*)h;
    }
}

// ---------------- rmsnorm(conv + bias) -> fp16, warp per row ----------------
__global__ void rmsnorm_pre_k(const float* __restrict__ pre_g,
                              const float* __restrict__ conv_b)
{
    int row  = blockIdx.x*8 + (threadIdx.x >> 5);
    int lane = threadIdx.x & 31;
    const __half* r = g_xconvh + (size_t)row*DIM + lane*16;
    uint4 u0 = *(const uint4*)r;
    uint4 u1 = *(const uint4*)(r + 8);
    float4 b0 = *(const float4*)&conv_b[lane*16];
    float4 b1 = *(const float4*)&conv_b[lane*16+4];
    float4 b2 = *(const float4*)&conv_b[lane*16+8];
    float4 b3 = *(const float4*)&conv_b[lane*16+12];
    __half2* h0 = (__half2*)&u0;
    __half2* h1 = (__half2*)&u1;
    float v[16];
    #pragma unroll
    for (int i=0;i<4;i++){
        float2 f = __half22float2(h0[i]); v[2*i]=f.x; v[2*i+1]=f.y;
        float2 g = __half22float2(h1[i]); v[8+2*i]=g.x; v[8+2*i+1]=g.y;
    }
    float bias[16] = {b0.x,b0.y,b0.z,b0.w,b1.x,b1.y,b1.z,b1.w,
                      b2.x,b2.y,b2.z,b2.w,b3.x,b3.y,b3.z,b3.w};
    float ss = 0.f;
    #pragma unroll
    for (int i=0;i<16;i++){ v[i] += bias[i]; ss += v[i]*v[i]; }
    ss = warp_sum(ss);
    float rr = rsqrtf(ss * (1.f/DIM) + 1e-6f);
    float4 g0 = *(const float4*)&pre_g[lane*16];
    float4 g1 = *(const float4*)&pre_g[lane*16+4];
    float4 g2 = *(const float4*)&pre_g[lane*16+8];
    float4 g3 = *(const float4*)&pre_g[lane*16+12];
    float gg[16] = {g0.x,g0.y,g0.z,g0.w,g1.x,g1.y,g1.z,g1.w,
                    g2.x,g2.y,g2.z,g2.w,g3.x,g3.y,g3.z,g3.w};
    __half2 o[8];
    #pragma unroll
    for (int i=0;i<8;i++)
        o[i] = __floats2half2_rn(v[2*i]*rr*gg[2*i], v[2*i+1]*rr*gg[2*i+1]);
    __half* w = g_xnorm + (size_t)row*DIM + lane*16;
    *(uint4*)w       = *(uint4*)&o[0];
    *(uint4*)(w + 8) = *(uint4*)&o[4];
}

// ---------------- rmsnorm + rope on q/k -> fp16, v passthrough; warp per row ----------------
__global__ void qkv_post_k(const float* __restrict__ q_g, const float* __restrict__ k_g)
{
    int row  = blockIdx.x*8 + (threadIdx.x >> 5);
    int lane = threadIdx.x & 31;
    int s = row & (SEQ-1);
    const __half* r = g_qkvh + (size_t)row*3*DIM + lane*16;
    uint4 q0 = *(const uint4*)r;
    uint4 q1 = *(const uint4*)(r + 8);
    uint4 k0 = *(const uint4*)(r + DIM);
    uint4 k1 = *(const uint4*)(r + DIM + 8);
    uint4 v0 = *(const uint4*)(r + 2*DIM);
    uint4 v1 = *(const uint4*)(r + 2*DIM + 8);
    float q[16], k[16];
    {
        __half2* hq0=(__half2*)&q0; __half2* hq1=(__half2*)&q1;
        __half2* hk0=(__half2*)&k0; __half2* hk1=(__half2*)&k1;
        #pragma unroll
        for (int i=0;i<4;i++){
            float2 f;
            f=__half22float2(hq0[i]); q[2*i]=f.x; q[2*i+1]=f.y;
            f=__half22float2(hq1[i]); q[8+2*i]=f.x; q[8+2*i+1]=f.y;
            f=__half22float2(hk0[i]); k[2*i]=f.x; k[2*i+1]=f.y;
            f=__half22float2(hk1[i]); k[8+2*i]=f.x; k[8+2*i+1]=f.y;
        }
    }
    float sq=0.f, sk=0.f;
    #pragma unroll
    for (int i=0;i<16;i++){ sq += q[i]*q[i]; sk += k[i]*k[i]; }
    sq = warp_sum(sq); sk = warp_sum(sk);
    float rq = rsqrtf(sq * (1.f/DIM) + 1e-6f);
    float rk = rsqrtf(sk * (1.f/DIM) + 1e-6f);

    float4 c0 = *(const float4*)&g_cos[s*HALF + lane*8];
    float4 c1 = *(const float4*)&g_cos[s*HALF + lane*8 + 4];
    float4 s0 = *(const float4*)&g_sin[s*HALF + lane*8];
    float4 s1 = *(const float4*)&g_sin[s*HALF + lane*8 + 4];
    float cs[8] = {c0.x,c0.y,c0.z,c0.w,c1.x,c1.y,c1.z,c1.w};
    float sn[8] = {s0.x,s0.y,s0.z,s0.w,s1.x,s1.y,s1.z,s1.w};
    float4 qg0 = *(const float4*)&q_g[lane*16];
    float4 qg1 = *(const float4*)&q_g[lane*16+4];
    float4 qg2 = *(const float4*)&q_g[lane*16+8];
    float4 qg3 = *(const float4*)&q_g[lane*16+12];
    float4 kg0 = *(const float4*)&k_g[lane*16];
    float4 kg1 = *(const float4*)&k_g[lane*16+4];
    float4 kg2 = *(const float4*)&k_g[lane*16+8];
    float4 kg3 = *(const float4*)&k_g[lane*16+12];
    float qg[16] = {qg0.x,qg0.y,qg0.z,qg0.w,qg1.x,qg1.y,qg1.z,qg1.w,
                    qg2.x,qg2.y,qg2.z,qg2.w,qg3.x,qg3.y,qg3.z,qg3.w};
    float kg[16] = {kg0.x,kg0.y,kg0.z,kg0.w,kg1.x,kg1.y,kg1.z,kg1.w,
                    kg2.x,kg2.y,kg2.z,kg2.w,kg3.x,kg3.y,kg3.z,kg3.w};

    __half2 qo[8], ko[8];
    #pragma unroll
    for (int j=0;j<8;j++){
        float x0 = q[2*j]*rq*qg[2*j], x1 = q[2*j+1]*rq*qg[2*j+1];
        qo[j] = __floats2half2_rn(x0*cs[j] - x1*sn[j], x0*sn[j] + x1*cs[j]);
        float y0 = k[2*j]*rk*kg[2*j], y1 = k[2*j+1]*rk*kg[2*j+1];
        ko[j] = __floats2half2_rn(y0*cs[j] - y1*sn[j], y0*sn[j] + y1*cs[j]);
    }
    __half* wq = g_q + (size_t)row*DIM + lane*16;
    __half* wk = g_k + (size_t)row*DIM + lane*16;
    __half* wv = g_v + (size_t)row*DIM + lane*16;
    *(uint4*)wq = *(uint4*)&qo[0];  *(uint4*)(wq+8) = *(uint4*)&qo[4];
    *(uint4*)wk = *(uint4*)&ko[0];  *(uint4*)(wk+8) = *(uint4*)&ko[4];
    *(uint4*)wv = v0;               *(uint4*)(wv+8) = v1;
}

// ---------------- fused softmax + colsum ----------------
// Block: 32 rows of one batch x 2048 cols, 256 threads (thread owns 8 cols).
// Logits bounded (|s| <= 22.7) so exp needs no max subtraction.
// wbar[b,k] += sum over rows of exp(s)/Z_row, via one atomicAdd per col per block.
#define SC_ROWS 32
__global__ void softmax_colsum_k()
{
    int row0 = blockIdx.x * SC_ROWS;
    int b = row0 >> 11;               // /SEQ
    int tid = threadIdx.x;            // 256
    int c0 = tid * 8;
    __shared__ float ssum[2][8];
    float acc[8] = {0,0,0,0,0,0,0,0};
    const __half* base = g_scoresh + (size_t)row0*SEQ + c0;
    #pragma unroll 1
    for (int r = 0; r < SC_ROWS; r++){
        uint4 u = *(const uint4*)(base + (size_t)r*SEQ);
        __half2* h = (__half2*)&u;
        float v[8];
        #pragma unroll
        for (int i=0;i<4;i++){ float2 f=__half22float2(h[i]); v[2*i]=f.x; v[2*i+1]=f.y; }
        float s = 0.f;
        #pragma unroll
        for (int i=0;i<8;i++){ v[i] = fast_exp(v[i]); s += v[i]; }
        s = warp_sum(s);
        if ((tid&31)==0) ssum[r&1][tid>>5] = s;
        __syncthreads();
        float Z = ssum[r&1][0];
        #pragma unroll
        for (int w=1;w<8;w++) Z += ssum[r&1][w];
        float iz = __frcp_rn(Z);
        #pragma unroll
        for (int i=0;i<8;i++) acc[i] += v[i]*iz;
    }
    float* wb = g_wbar + b*SEQ + c0;
    #pragma unroll
    for (int i=0;i<8;i++) atomicAdd(wb + i, acc[i]);
}

// ---------------- final reduction (fp16 x and v) ----------------
__global__ void final_acc_k()
{
    int b = blockIdx.y, c = blockIdx.x;
    int t = threadIdx.x;              // 256, half2 lanes
    size_t base2 = (((size_t)b*SEQ + (size_t)c*128)*DIM >> 1) + t;
    const __half2* xh2 = (const __half2*)g_xh;
    const __half2* v2  = (const __half2*)g_v;
    const float* wb = g_wbar + b*SEQ + c*128;
    float ax=0.f, ay=0.f;
    #pragma unroll 4
    for (int s=0;s<128;s++){
        float2 xf = __half22float2(xh2[base2 + (size_t)s*(DIM/2)]);
        float2 vf = __half22float2(v2 [base2 + (size_t)s*(DIM/2)]);
        float w = wb[s];
        ax += xf.x + w*vf.x;
        ay += xf.y + w*vf.y;
    }
    g_part[(b*16+c)*DIM + 2*t]   = ax;
    g_part[(b*16+c)*DIM + 2*t+1] = ay;
}
__global__ void final_reduce_k(float* __restrict__ out)
{
    int b = blockIdx.x, d = threadIdx.x;
    float a = 0.f;
    #pragma unroll
    for (int c=0;c<16;c++) a += g_part[(b*16+c)*DIM + d];
    out[b*DIM + d] = a * (1.f/SEQ);
}

// ---------------- launch ----------------
extern "C" void kernel_launch(void* const* d_in, const int* in_sizes, int n_in,
                              void* d_out, int out_size)
{
    const float* x      = (const float*)d_in[0];
    const float* conv_w = (const float*)d_in[1];
    const float* conv_b = (const float*)d_in[2];
    const float* pre_g  = (const float*)d_in[3];
    const float* q_g    = (const float*)d_in[4];
    const float* k_g    = (const float*)d_in[5];
    const float* Wq     = (const float*)d_in[6];
    const float* Wk     = (const float*)d_in[7];
    const float* Wv     = (const float*)d_in[8];
    float* out = (float*)d_out;

    __half *xh, *wch, *wqkvh, *xconvh, *xnorm, *qkvh, *q, *k, *scoresh;
    cudaGetSymbolAddress((void**)&xh, g_xh);
    cudaGetSymbolAddress((void**)&wch, g_wch);
    cudaGetSymbolAddress((void**)&wqkvh, g_wqkvh);
    cudaGetSymbolAddress((void**)&xconvh, g_xconvh);
    cudaGetSymbolAddress((void**)&xnorm, g_xnorm);
    cudaGetSymbolAddress((void**)&qkvh, g_qkvh);
    cudaGetSymbolAddress((void**)&q, g_q);
    cudaGetSymbolAddress((void**)&k, g_k);
    cudaGetSymbolAddress((void**)&scoresh, g_scoresh);

    cudaFuncSetAttribute(mma_gemm_k<0>, cudaFuncAttributeMaxDynamicSharedMemorySize, GSMEM);
    cudaFuncSetAttribute(mma_gemm_k<1>, cudaFuncAttributeMaxDynamicSharedMemorySize, GSMEM);
    cudaFuncSetAttribute(mma_gemm_k<2>, cudaFuncAttributeMaxDynamicSharedMemorySize, GSMEM);

    cvt_x_k<<<MR*DIM/8/256, 256>>>(x);
    prep_weights<<<(3*DIM*DIM + 255)/256, 256>>>(conv_w, Wq, Wk, Wv);
    rope_tables_k<<<SEQ, HALF>>>();
    zero_wbar_k<<<MR/256, 256>>>();

    // conv: M=16384, N=512, K=1536
    mma_gemm_k<1><<<dim3(DIM/128, MR/128), 256, GSMEM>>>(xh, wch, xconvh, DIM, 3*DIM, 1.f);
    rmsnorm_pre_k<<<MR/8, 256>>>(pre_g, conv_b);

    // qkv: M=16384, N=1536, K=512
    mma_gemm_k<0><<<dim3(3*DIM/128, MR/128), 256, GSMEM>>>(xnorm, wqkvh, qkvh, 3*DIM, DIM, 1.f);
    qkv_post_k<<<MR/8, 256>>>(q_g, k_g);

    // scores: per-batch NT, M=N=2048, K=512, fp16 logits
    mma_gemm_k<2><<<dim3(SEQ/128, SEQ/128, BATCH), 256, GSMEM>>>(q, k, scoresh, SEQ, DIM,
                                                                 0.044194173824159216f);
    softmax_colsum_k<<<MR/SC_ROWS, 256>>>();
    final_acc_k<<<dim3(16, BATCH), 256>>>();
    final_reduce_k<<<BATCH, DIM>>>(out);
}

// round 7
// speedup vs baseline: 5.6007x; 1.2053x over previous
#include <cuda_runtime.h>
#include <cuda_fp16.h>
#include <cstdint>
#include <math.h>
#include <mma.h>

using namespace nvcuda;

#define BATCH 8
#define SEQ   2048
#define DIM   512
#define MR    (BATCH*SEQ)
#define HALF  (DIM/2)

// ---------------- static scratch ----------------
__device__ __half g_xh[(size_t)MR*DIM];         // x fp16 (im2col source + final acc)
__device__ __half g_wch[3*DIM*DIM];             // conv weights [dout][k=1536] K-major fp16
__device__ __half g_wqkvh[3*DIM*DIM];           // concat(Wq,Wk,Wv) [e=1536][d=512] fp16
__device__ __half g_xconvh[(size_t)MR*DIM];     // conv output fp16 (pre-bias)
__device__ __half g_xnorm[(size_t)MR*DIM];      // rmsnorm(conv+bias) fp16
__device__ __half g_qkvh[(size_t)MR*3*DIM];     // raw q|k|v fp16
__device__ __half g_q[(size_t)MR*DIM];          // normed+rope'd q fp16
__device__ __half g_k[(size_t)MR*DIM];          // normed+rope'd k fp16
__device__ __half g_v[(size_t)MR*DIM];          // v fp16
__device__ __half g_scoresh[(size_t)BATCH*SEQ*SEQ];  // logits fp16 (bounded |s|<=22.7)
__device__ float  g_wbar[MR];
__device__ double g_inv[HALF];
__device__ float  g_cos[SEQ*HALF];
__device__ float  g_sin[SEQ*HALF];
__device__ float  g_part[BATCH*16*DIM];

// ---------------- helpers ----------------
__device__ __forceinline__ uint32_t smem_u32(const void* p){
    uint32_t a;
    asm("{ .reg .u64 t; cvta.to.shared.u64 t, %1; cvt.u32.u64 %0, t; }" : "=r"(a) : "l"(p));
    return a;
}
__device__ __forceinline__ void cp_async16(uint32_t dst, const void* src, bool pred){
    int sz = pred ? 16 : 0;   // ZFILL when masked
    asm volatile("cp.async.cg.shared.global [%0], [%1], 16, %2;"
                 :: "r"(dst), "l"(src), "r"(sz));
}
__device__ __forceinline__ void cp_async_commit(){
    asm volatile("cp.async.commit_group;" ::: "memory");
}
template<int N>
__device__ __forceinline__ void cp_async_wait(){
    asm volatile("cp.async.wait_group %0;" :: "n"(N) : "memory");
}
__device__ __forceinline__ float warp_sum(float v){
    #pragma unroll
    for (int o=16;o;o>>=1) v += __shfl_xor_sync(0xffffffffu, v, o);
    return v;
}
// FMA-pipe exp. |rel err| ~2e-5. Valid for arg in [-87, 60]; here [-46, 23].
__device__ __forceinline__ float fast_exp(float x){
    float t = x * 1.4426950408889634f;
    t = fmaxf(t, -125.0f);
    float fl = floorf(t);
    float f = t - fl;
    float p = 1.5403530e-4f;
    p = fmaf(p, f, 1.3333558e-3f);
    p = fmaf(p, f, 9.6181291e-3f);
    p = fmaf(p, f, 5.5504109e-2f);
    p = fmaf(p, f, 2.4022651e-1f);
    p = fmaf(p, f, 6.9314718e-1f);
    p = fmaf(p, f, 1.0f);
    int i = (int)fl;
    return p * __int_as_float((i + 127) << 23);
}

// ---------------- input conversion (+ wbar zero) / weight re-layout ----------------
__global__ void cvt_x_k(const float* __restrict__ x)
{
    size_t flat = (size_t)blockIdx.x*256 + threadIdx.x;
    size_t i = flat * 8;
    float4 v0 = *(const float4*)&x[i];
    float4 v1 = *(const float4*)&x[i+4];
    __half2 h[4] = { __floats2half2_rn(v0.x,v0.y), __floats2half2_rn(v0.z,v0.w),
                     __floats2half2_rn(v1.x,v1.y), __floats2half2_rn(v1.z,v1.w) };
    *(uint4*)&g_xh[i] = *(uint4*)h;
    if (flat < MR) g_wbar[flat] = 0.f;
}

__global__ void prep_weights(const float* __restrict__ conv_w,
                             const float* __restrict__ Wq,
                             const float* __restrict__ Wk,
                             const float* __restrict__ Wv)
{
    int idx = blockIdx.x*256 + threadIdx.x;
    if (idx >= 3*DIM*DIM) return;
    {   // conv: [dout][kk], kk = t*512 + din
        int kk   = idx % (3*DIM);
        int dout = idx / (3*DIM);
        int din  = kk % DIM;
        int t    = kk / DIM;
        g_wch[idx] = __float2half_rn(conv_w[(dout*DIM + din)*3 + t]);
    }
    {   // qkv concat
        float w = (idx < DIM*DIM) ? Wq[idx]
                : (idx < 2*DIM*DIM) ? Wk[idx - DIM*DIM]
                : Wv[idx - 2*DIM*DIM];
        g_wqkvh[idx] = __float2half_rn(w);
    }
}

// fp64 pow only 256 times; tables via double range-reduction + float sincos.
__global__ void rope_inv_k()
{
    int i = threadIdx.x;
    g_inv[i] = pow(10000.0, -((double)(2*i)) / 512.0);
}
__global__ void rope_tables_k()
{
    int i = threadIdx.x;   // 0..255
    int s = blockIdx.x;    // 0..2047
    double arg = (double)s * g_inv[i];
    const double TWO_PI = 6.283185307179586476925;
    double red = arg - rint(arg * (1.0/TWO_PI)) * TWO_PI;   // [-pi, pi]
    float rf = (float)red;
    float sn, cs;
    __sincosf(rf, &sn, &cs);   // small-arg: fast MUFU path, ~1e-6 abs err
    g_cos[s*HALF + i] = cs;
    g_sin[s*HALF + i] = sn;
}

// ---------------- fp16 WMMA GEMM: block 128x256x32, warp tile 64x64 ----------------
// C[M,N] = A[M,K] * B[N,K]^T, f32 accumulate, fp16 C.
// MODE 0: generic.  MODE 1: A = implicit im2col (conv).  MODE 2: batched via z, scale on acc.
#define TLDH   40
#define A_BYT  (128*TLDH*2)          // 10240
#define STG_B  ((128+256)*TLDH*2)    // 30720
#define ELD    260                   // epilogue f32 tile ld (64 x 260 x 4 = 66560)
#define GSMEM  (3*STG_B)             // 92160

template<int MODE>
__global__ __launch_bounds__(256,1) void mma_gemm_k(
    const __half* __restrict__ Ah, const __half* __restrict__ Bh,
    __half* __restrict__ Ch, int Nd, int Kd, float scale)
{
    extern __shared__ __half smh[];
    const uint32_t sb = smem_u32(smh);
    const int tid = threadIdx.x;
    const int wid = tid >> 5;
    const int wm = wid & 1, wn = wid >> 1;           // 2 x 4 warps, warp tile 64x64
    const int bm = blockIdx.y*128, bn = blockIdx.x*256;
    if (MODE == 2) {
        size_t z = blockIdx.z;
        Ah += z * (size_t)SEQ * DIM;
        Bh += z * (size_t)SEQ * DIM;
        Ch += z * (size_t)SEQ * SEQ;
    }

    wmma::fragment<wmma::accumulator,16,16,16,float> acc[4][4];
    #pragma unroll
    for (int i=0;i<4;i++)
        #pragma unroll
        for (int j=0;j<4;j++) wmma::fill_fragment(acc[i][j], 0.f);

    const int nIter = Kd / 32;

    auto load_tiles = [&](int it, int stg){
        const int k0 = it*32;
        const uint32_t abase = sb + stg*STG_B;
        const uint32_t bbase = abase + A_BYT;
        // A: 128 rows x 32 halfs
        #pragma unroll
        for (int l=0;l<2;l++){
            int i   = l*256 + tid;
            int row = i >> 2;
            int kq  = (i & 3) * 8;
            const __half* src; bool pred = true;
            if (MODE == 1) {
                int gm = bm + row;
                int s  = gm & (SEQ-1);
                int kg = k0 + kq;
                int t  = kg >> 9;
                pred = !((s==0 && t==0) || (s==SEQ-1 && t==2));
                src = pred ? (Ah + (size_t)gm*DIM + kg - DIM) : Ah;
            } else {
                src = Ah + (size_t)(bm+row)*Kd + k0 + kq;
            }
            cp_async16(abase + (row*TLDH + kq)*2, src, pred);
        }
        // B: 256 rows x 32 halfs
        #pragma unroll
        for (int l=0;l<4;l++){
            int i   = l*256 + tid;
            int row = i >> 2;
            int kq  = (i & 3) * 8;
            cp_async16(bbase + (row*TLDH + kq)*2,
                       Bh + (size_t)(bn+row)*Kd + k0 + kq, true);
        }
    };

    load_tiles(0, 0); cp_async_commit();
    load_tiles(1, 1); cp_async_commit();

    for (int it = 0; it < nIter; ++it) {
        cp_async_wait<1>();
        __syncthreads();
        const int stg = it % 3;
        const __half* Ab = smh + stg*(STG_B/2);
        const __half* Bb = Ab + 128*TLDH;
        #pragma unroll
        for (int ks = 0; ks < 2; ks++) {
            wmma::fragment<wmma::matrix_b,16,16,16,__half,wmma::col_major> bf[4];
            #pragma unroll
            for (int j=0;j<4;j++)
                wmma::load_matrix_sync(bf[j], Bb + (wn*64 + j*16)*TLDH + ks*16, TLDH);
            #pragma unroll
            for (int i=0;i<4;i++){
                wmma::fragment<wmma::matrix_a,16,16,16,__half,wmma::row_major> af;
                wmma::load_matrix_sync(af, Ab + (wm*64 + i*16)*TLDH + ks*16, TLDH);
                #pragma unroll
                for (int j=0;j<4;j++)
                    wmma::mma_sync(acc[i][j], af, bf[j], acc[i][j]);
            }
        }
        if (it + 2 < nIter) load_tiles(it+2, (it+2)%3);
        cp_async_commit();
    }

    if (MODE == 2) {
        #pragma unroll
        for (int i=0;i<4;i++)
            #pragma unroll
            for (int j=0;j<4;j++)
                #pragma unroll
                for (int e=0;e<acc[i][j].num_elements;e++) acc[i][j].x[e] *= scale;
    }

    // fp16 C via 64x260 f32 smem tile, two M-half passes
    cp_async_wait<0>();
    __syncthreads();
    float* eb = (float*)smh;
    #pragma unroll
    for (int h=0; h<2; h++){
        if (wm == h) {
            #pragma unroll
            for (int i=0;i<4;i++)
                #pragma unroll
                for (int j=0;j<4;j++)
                    wmma::store_matrix_sync(eb + (i*16)*ELD + wn*64 + j*16,
                                            acc[i][j], ELD, wmma::mem_row_major);
        }
        __syncthreads();
        #pragma unroll
        for (int p=0;p<8;p++){
            int e = p*256 + tid;          // 0..2047 chunks of 8 cols
            int row = e >> 5;
            int c0 = (e & 31) * 8;
            float4 a = *(float4*)&eb[row*ELD + c0];
            float4 b = *(float4*)&eb[row*ELD + c0 + 4];
            __half2 hh[4] = { __floats2half2_rn(a.x,a.y), __floats2half2_rn(a.z,a.w),
                              __floats2half2_rn(b.x,b.y), __floats2half2_rn(b.z,b.w) };
            *(uint4*)&Ch[(size_t)(bm + h*64 + row)*Nd + bn + c0] = *(uint4*)hh;
        }
        __syncthreads();
    }
}

// ---------------- rmsnorm(conv + bias) -> fp16, warp per row ----------------
__global__ void rmsnorm_pre_k(const float* __restrict__ pre_g,
                              const float* __restrict__ conv_b)
{
    int row  = blockIdx.x*8 + (threadIdx.x >> 5);
    int lane = threadIdx.x & 31;
    const __half* r = g_xconvh + (size_t)row*DIM + lane*16;
    uint4 u0 = *(const uint4*)r;
    uint4 u1 = *(const uint4*)(r + 8);
    float4 b0 = *(const float4*)&conv_b[lane*16];
    float4 b1 = *(const float4*)&conv_b[lane*16+4];
    float4 b2 = *(const float4*)&conv_b[lane*16+8];
    float4 b3 = *(const float4*)&conv_b[lane*16+12];
    __half2* h0 = (__half2*)&u0;
    __half2* h1 = (__half2*)&u1;
    float v[16];
    #pragma unroll
    for (int i=0;i<4;i++){
        float2 f = __half22float2(h0[i]); v[2*i]=f.x; v[2*i+1]=f.y;
        float2 g = __half22float2(h1[i]); v[8+2*i]=g.x; v[8+2*i+1]=g.y;
    }
    float bias[16] = {b0.x,b0.y,b0.z,b0.w,b1.x,b1.y,b1.z,b1.w,
                      b2.x,b2.y,b2.z,b2.w,b3.x,b3.y,b3.z,b3.w};
    float ss = 0.f;
    #pragma unroll
    for (int i=0;i<16;i++){ v[i] += bias[i]; ss += v[i]*v[i]; }
    ss = warp_sum(ss);
    float rr = rsqrtf(ss * (1.f/DIM) + 1e-6f);
    float4 g0 = *(const float4*)&pre_g[lane*16];
    float4 g1 = *(const float4*)&pre_g[lane*16+4];
    float4 g2 = *(const float4*)&pre_g[lane*16+8];
    float4 g3 = *(const float4*)&pre_g[lane*16+12];
    float gg[16] = {g0.x,g0.y,g0.z,g0.w,g1.x,g1.y,g1.z,g1.w,
                    g2.x,g2.y,g2.z,g2.w,g3.x,g3.y,g3.z,g3.w};
    __half2 o[8];
    #pragma unroll
    for (int i=0;i<8;i++)
        o[i] = __floats2half2_rn(v[2*i]*rr*gg[2*i], v[2*i+1]*rr*gg[2*i+1]);
    __half* w = g_xnorm + (size_t)row*DIM + lane*16;
    *(uint4*)w       = *(uint4*)&o[0];
    *(uint4*)(w + 8) = *(uint4*)&o[4];
}

// ---------------- rmsnorm + rope on q/k -> fp16, v passthrough; warp per row ----------------
__global__ void qkv_post_k(const float* __restrict__ q_g, const float* __restrict__ k_g)
{
    int row  = blockIdx.x*8 + (threadIdx.x >> 5);
    int lane = threadIdx.x & 31;
    int s = row & (SEQ-1);
    const __half* r = g_qkvh + (size_t)row*3*DIM + lane*16;
    uint4 q0 = *(const uint4*)r;
    uint4 q1 = *(const uint4*)(r + 8);
    uint4 k0 = *(const uint4*)(r + DIM);
    uint4 k1 = *(const uint4*)(r + DIM + 8);
    uint4 v0 = *(const uint4*)(r + 2*DIM);
    uint4 v1 = *(const uint4*)(r + 2*DIM + 8);
    float q[16], k[16];
    {
        __half2* hq0=(__half2*)&q0; __half2* hq1=(__half2*)&q1;
        __half2* hk0=(__half2*)&k0; __half2* hk1=(__half2*)&k1;
        #pragma unroll
        for (int i=0;i<4;i++){
            float2 f;
            f=__half22float2(hq0[i]); q[2*i]=f.x; q[2*i+1]=f.y;
            f=__half22float2(hq1[i]); q[8+2*i]=f.x; q[8+2*i+1]=f.y;
            f=__half22float2(hk0[i]); k[2*i]=f.x; k[2*i+1]=f.y;
            f=__half22float2(hk1[i]); k[8+2*i]=f.x; k[8+2*i+1]=f.y;
        }
    }
    float sq=0.f, sk=0.f;
    #pragma unroll
    for (int i=0;i<16;i++){ sq += q[i]*q[i]; sk += k[i]*k[i]; }
    sq = warp_sum(sq); sk = warp_sum(sk);
    float rq = rsqrtf(sq * (1.f/DIM) + 1e-6f);
    float rk = rsqrtf(sk * (1.f/DIM) + 1e-6f);

    float4 c0 = *(const float4*)&g_cos[s*HALF + lane*8];
    float4 c1 = *(const float4*)&g_cos[s*HALF + lane*8 + 4];
    float4 s0 = *(const float4*)&g_sin[s*HALF + lane*8];
    float4 s1 = *(const float4*)&g_sin[s*HALF + lane*8 + 4];
    float cs[8] = {c0.x,c0.y,c0.z,c0.w,c1.x,c1.y,c1.z,c1.w};
    float sn[8] = {s0.x,s0.y,s0.z,s0.w,s1.x,s1.y,s1.z,s1.w};
    float4 qg0 = *(const float4*)&q_g[lane*16];
    float4 qg1 = *(const float4*)&q_g[lane*16+4];
    float4 qg2 = *(const float4*)&q_g[lane*16+8];
    float4 qg3 = *(const float4*)&q_g[lane*16+12];
    float4 kg0 = *(const float4*)&k_g[lane*16];
    float4 kg1 = *(const float4*)&k_g[lane*16+4];
    float4 kg2 = *(const float4*)&k_g[lane*16+8];
    float4 kg3 = *(const float4*)&k_g[lane*16+12];
    float qg[16] = {qg0.x,qg0.y,qg0.z,qg0.w,qg1.x,qg1.y,qg1.z,qg1.w,
                    qg2.x,qg2.y,qg2.z,qg2.w,qg3.x,qg3.y,qg3.z,qg3.w};
    float kg[16] = {kg0.x,kg0.y,kg0.z,kg0.w,kg1.x,kg1.y,kg1.z,kg1.w,
                    kg2.x,kg2.y,kg2.z,kg2.w,kg3.x,kg3.y,kg3.z,kg3.w};

    __half2 qo[8], ko[8];
    #pragma unroll
    for (int j=0;j<8;j++){
        float x0 = q[2*j]*rq*qg[2*j], x1 = q[2*j+1]*rq*qg[2*j+1];
        qo[j] = __floats2half2_rn(x0*cs[j] - x1*sn[j], x0*sn[j] + x1*cs[j]);
        float y0 = k[2*j]*rk*kg[2*j], y1 = k[2*j+1]*rk*kg[2*j+1];
        ko[j] = __floats2half2_rn(y0*cs[j] - y1*sn[j], y0*sn[j] + y1*cs[j]);
    }
    __half* wq = g_q + (size_t)row*DIM + lane*16;
    __half* wk = g_k + (size_t)row*DIM + lane*16;
    __half* wv = g_v + (size_t)row*DIM + lane*16;
    *(uint4*)wq = *(uint4*)&qo[0];  *(uint4*)(wq+8) = *(uint4*)&qo[4];
    *(uint4*)wk = *(uint4*)&ko[0];  *(uint4*)(wk+8) = *(uint4*)&ko[4];
    *(uint4*)wv = v0;               *(uint4*)(wv+8) = v1;
}

// ---------------- fused softmax + colsum ----------------
#define SC_ROWS 32
__global__ void softmax_colsum_k()
{
    int row0 = blockIdx.x * SC_ROWS;
    int b = row0 >> 11;
    int tid = threadIdx.x;            // 256
    int c0 = tid * 8;
    __shared__ float ssum[2][8];
    float acc[8] = {0,0,0,0,0,0,0,0};
    const __half* base = g_scoresh + (size_t)row0*SEQ + c0;
    #pragma unroll 1
    for (int r = 0; r < SC_ROWS; r++){
        uint4 u = *(const uint4*)(base + (size_t)r*SEQ);
        __half2* h = (__half2*)&u;
        float v[8];
        #pragma unroll
        for (int i=0;i<4;i++){ float2 f=__half22float2(h[i]); v[2*i]=f.x; v[2*i+1]=f.y; }
        float s = 0.f;
        #pragma unroll
        for (int i=0;i<8;i++){ v[i] = fast_exp(v[i]); s += v[i]; }
        s = warp_sum(s);
        if ((tid&31)==0) ssum[r&1][tid>>5] = s;
        __syncthreads();
        float Z = ssum[r&1][0];
        #pragma unroll
        for (int w=1;w<8;w++) Z += ssum[r&1][w];
        float iz = __frcp_rn(Z);
        #pragma unroll
        for (int i=0;i<8;i++) acc[i] += v[i]*iz;
    }
    float* wb = g_wbar + b*SEQ + c0;
    #pragma unroll
    for (int i=0;i<8;i++) atomicAdd(wb + i, acc[i]);
}

// ---------------- final reduction (fp16 x and v) ----------------
__global__ void final_acc_k()
{
    int b = blockIdx.y, c = blockIdx.x;
    int t = threadIdx.x;              // 256, half2 lanes
    size_t base2 = (((size_t)b*SEQ + (size_t)c*128)*DIM >> 1) + t;
    const __half2* xh2 = (const __half2*)g_xh;
    const __half2* v2  = (const __half2*)g_v;
    const float* wb = g_wbar + b*SEQ + c*128;
    float ax=0.f, ay=0.f;
    #pragma unroll 4
    for (int s=0;s<128;s++){
        float2 xf = __half22float2(xh2[base2 + (size_t)s*(DIM/2)]);
        float2 vf = __half22float2(v2 [base2 + (size_t)s*(DIM/2)]);
        float w = wb[s];
        ax += xf.x + w*vf.x;
        ay += xf.y + w*vf.y;
    }
    g_part[(b*16+c)*DIM + 2*t]   = ax;
    g_part[(b*16+c)*DIM + 2*t+1] = ay;
}
__global__ void final_reduce_k(float* __restrict__ out)
{
    int b = blockIdx.x, d = threadIdx.x;
    float a = 0.f;
    #pragma unroll
    for (int c=0;c<16;c++) a += g_part[(b*16+c)*DIM + d];
    out[b*DIM + d] = a * (1.f/SEQ);
}

// ---------------- launch ----------------
extern "C" void kernel_launch(void* const* d_in, const int* in_sizes, int n_in,
                              void* d_out, int out_size)
{
    const float* x      = (const float*)d_in[0];
    const float* conv_w = (const float*)d_in[1];
    const float* conv_b = (const float*)d_in[2];
    const float* pre_g  = (const float*)d_in[3];
    const float* q_g    = (const float*)d_in[4];
    const float* k_g    = (const float*)d_in[5];
    const float* Wq     = (const float*)d_in[6];
    const float* Wk     = (const float*)d_in[7];
    const float* Wv     = (const float*)d_in[8];
    float* out = (float*)d_out;

    __half *xh, *wch, *wqkvh, *xconvh, *xnorm, *qkvh, *q, *k, *scoresh;
    cudaGetSymbolAddress((void**)&xh, g_xh);
    cudaGetSymbolAddress((void**)&wch, g_wch);
    cudaGetSymbolAddress((void**)&wqkvh, g_wqkvh);
    cudaGetSymbolAddress((void**)&xconvh, g_xconvh);
    cudaGetSymbolAddress((void**)&xnorm, g_xnorm);
    cudaGetSymbolAddress((void**)&qkvh, g_qkvh);
    cudaGetSymbolAddress((void**)&q, g_q);
    cudaGetSymbolAddress((void**)&k, g_k);
    cudaGetSymbolAddress((void**)&scoresh, g_scoresh);

    cudaFuncSetAttribute(mma_gemm_k<0>, cudaFuncAttributeMaxDynamicSharedMemorySize, GSMEM);
    cudaFuncSetAttribute(mma_gemm_k<1>, cudaFuncAttributeMaxDynamicSharedMemorySize, GSMEM);
    cudaFuncSetAttribute(mma_gemm_k<2>, cudaFuncAttributeMaxDynamicSharedMemorySize, GSMEM);

    cvt_x_k<<<MR*DIM/8/256, 256>>>(x);
    prep_weights<<<(3*DIM*DIM + 255)/256, 256>>>(conv_w, Wq, Wk, Wv);
    rope_inv_k<<<1, HALF>>>();
    rope_tables_k<<<SEQ, HALF>>>();

    // conv: M=16384, N=512, K=1536
    mma_gemm_k<1><<<dim3(DIM/256, MR/128), 256, GSMEM>>>(xh, wch, xconvh, DIM, 3*DIM, 1.f);
    rmsnorm_pre_k<<<MR/8, 256>>>(pre_g, conv_b);

    // qkv: M=16384, N=1536, K=512
    mma_gemm_k<0><<<dim3(3*DIM/256, MR/128), 256, GSMEM>>>(xnorm, wqkvh, qkvh, 3*DIM, DIM, 1.f);
    qkv_post_k<<<MR/8, 256>>>(q_g, k_g);

    // scores: per-batch NT, M=N=2048, K=512, fp16 logits
    mma_gemm_k<2><<<dim3(SEQ/256, SEQ/128, BATCH), 256, GSMEM>>>(q, k, scoresh, SEQ, DIM,
                                                                 0.044194173824159216f);
    softmax_colsum_k<<<MR/SC_ROWS, 256>>>();
    final_acc_k<<<dim3(16, BATCH), 256>>>();
    final_reduce_k<<<BATCH, DIM>>>(out);
}